// round 14
// baseline (speedup 1.0000x reference)
#include <cuda_runtime.h>
#include <cuda_bf16.h>
#include <math.h>
#include <stdint.h>

#define BB 2
#define LL 512
#define LCC 64
#define DM 768
#define DI 1536
#define NH 24
#define HD 64
#define DSTATE 128
#define CONVD 1792
#define DIP 3352
#define NLAYER 8
#define AHH 8
#define ADD 64
#define AINNER 512

typedef __nv_bfloat16 bf16;

// ---------------- scratch ----------------
__device__ float g_hidden[BB*LL*DM];
__device__ float g_resid [BB*LL*DM];
__device__ float g_zx    [BB*LL*DIP];
__device__ float g_xBC   [BB*LL*CONVD];
__device__ float g_dt    [BB*LL*NH];
__device__ float g_dA    [BB*LL*NH];
__device__ float g_y     [BB*LL*DI];
__device__ float g_q     [BB*LL*AINNER];
__device__ float g_kall  [NLAYER*BB*LCC*AINNER];
__device__ float g_vall  [NLAYER*BB*LCC*AINNER];
__device__ float g_aff   [NLAYER*BB*6*DM];
__device__ float g_csilu [BB*DM];

__device__ bf16 g_u_bf [BB*LL*DM];
__device__ bf16 g_y_bf [BB*LL*DI];
__device__ bf16 g_ao_bf[BB*LL*AINNER];
__device__ bf16 g_ref_bf[BB*LCC*DM];

__device__ bf16 g_wi_bf[NLAYER*DM*DIP];
__device__ bf16 g_wo_bf[NLAYER*DI*DM];
__device__ bf16 g_wq_bf[NLAYER*DM*AINNER];
__device__ bf16 g_wk_bf[NLAYER*DM*AINNER];
__device__ bf16 g_wv_bf[NLAYER*DM*AINNER];
__device__ bf16 g_wp_bf[NLAYER*AINNER*DM];

__device__ __forceinline__ float siluf(float x) { return x / (1.f + expf(-x)); }

__device__ __forceinline__ float block_reduce_sum(float v) {
    __shared__ float red_s[33];
    int lane = threadIdx.x & 31;
    int wid  = threadIdx.x >> 5;
    #pragma unroll
    for (int o = 16; o > 0; o >>= 1) v += __shfl_xor_sync(0xffffffffu, v, o);
    if (lane == 0) red_s[wid] = v;
    __syncthreads();
    int nw = (blockDim.x + 31) >> 5;
    if (wid == 0) {
        float x = (lane < nw) ? red_s[lane] : 0.f;
        #pragma unroll
        for (int o = 16; o > 0; o >>= 1) x += __shfl_xor_sync(0xffffffffu, x, o);
        if (lane == 0) red_s[32] = x;
    }
    __syncthreads();
    float r = red_s[32];
    __syncthreads();
    return r;
}

__global__ void k_tobf16(const float* __restrict__ src, bf16* __restrict__ dst, int n) {
    int i = blockIdx.x * 256 + threadIdx.x;
    if (i < n) dst[i] = __float2bfloat16(src[i]);
}

__global__ void k_condsilu(const float* __restrict__ ref) {
    int i = blockIdx.x * 256 + threadIdx.x;
    if (i >= BB*DM) return;
    int b = i / DM, d = i % DM;
    float s = 0.f;
    for (int m = 0; m < LCC; m++) s += ref[(b*LCC + m)*DM + d];
    s *= (1.f / LCC);
    g_csilu[i] = siluf(s);
}

__global__ void k_ada(const float* __restrict__ ada_w, const float* __restrict__ ada_b) {
    int i = blockIdx.x * 256 + threadIdx.x;
    if (i >= NLAYER*BB*6*DM) return;
    int j  = i % (6*DM);
    int lb = i / (6*DM);
    int b  = lb % BB;
    int l  = lb / BB;
    float s = ada_b[l*6*DM + j];
    const float* cs = &g_csilu[b*DM];
    const float* w  = ada_w + (size_t)l*DM*6*DM + j;
    for (int d = 0; d < DM; d++) s += cs[d] * w[(size_t)d*6*DM];
    g_aff[i] = s;
}

// ================= bf16 tensor-core GEMM =================
__device__ __forceinline__ void ldsm4(uint32_t* r, uint32_t addr) {
    asm volatile("ldmatrix.sync.aligned.m8n8.x4.shared.b16 {%0,%1,%2,%3}, [%4];"
        : "=r"(r[0]), "=r"(r[1]), "=r"(r[2]), "=r"(r[3]) : "r"(addr));
}
__device__ __forceinline__ void ldsm4t(uint32_t* r, uint32_t addr) {
    asm volatile("ldmatrix.sync.aligned.m8n8.x4.trans.shared.b16 {%0,%1,%2,%3}, [%4];"
        : "=r"(r[0]), "=r"(r[1]), "=r"(r[2]), "=r"(r[3]) : "r"(addr));
}
__device__ __forceinline__ void mma_bf16(float* d, const uint32_t* a, uint32_t b0, uint32_t b1) {
    asm volatile("mma.sync.aligned.m16n8k16.row.col.f32.bf16.bf16.f32 "
        "{%0,%1,%2,%3}, {%4,%5,%6,%7}, {%8,%9}, {%0,%1,%2,%3};"
        : "+f"(d[0]), "+f"(d[1]), "+f"(d[2]), "+f"(d[3])
        : "r"(a[0]), "r"(a[1]), "r"(a[2]), "r"(a[3]), "r"(b0), "r"(b1));
}
__device__ __forceinline__ void cp16(void* smem, const void* gmem) {
    uint32_t s = (uint32_t)__cvta_generic_to_shared(smem);
    asm volatile("cp.async.cg.shared.global [%0], [%1], 16;" :: "r"(s), "l"(gmem));
}

#define AP 40
#define BP 136

// ---------------- 128x128 tile, 4-stage pipeline, 2 CTAs/SM, z-batched ----------------
#define OFF_B128 (128*AP)
#define STG128   (128*AP + 32*BP)
#define SM128_BYTES (4*STG128*2)   // 75776

__global__ __launch_bounds__(256, 2) void gemm128(const bf16* __restrict__ A,
                                                  const bf16* __restrict__ W,
                                                  float* __restrict__ C,
                                                  int M, int N, int K,
                                                  long wz, long cz) {
    extern __shared__ bf16 sm[];
    W += (size_t)blockIdx.z * wz;
    C += (size_t)blockIdx.z * cz;

    int tid = threadIdx.x;
    int n0 = blockIdx.x * 128, m0 = blockIdx.y * 128;
    int warp = tid >> 5, lane = tid & 31;
    int wm = warp >> 2, wn = warp & 3;

    int a_row = tid >> 1, a_off = (tid & 1) * 16;
    int b_row0 = tid >> 4, b_off = (tid & 15) * 8;

    float acc[4][4][4];
    #pragma unroll
    for (int i = 0; i < 4; i++)
        #pragma unroll
        for (int j = 0; j < 4; j++)
            #pragma unroll
            for (int v = 0; v < 4; v++) acc[i][j][v] = 0.f;

    int nt = K >> 5;

    auto load_tile = [&](int it, int st) {
        bf16* base = sm + st*STG128;
        const bf16* src = A + (size_t)(m0 + a_row)*K + it*32 + a_off;
        cp16(&base[a_row*AP + a_off],     src);
        cp16(&base[a_row*AP + a_off + 8], src + 8);
        #pragma unroll
        for (int s = 0; s < 2; s++) {
            int row = b_row0 + s*16;
            int col = n0 + b_off;
            if (col < N) {
                cp16(&base[OFF_B128 + row*BP + b_off], W + (size_t)(it*32 + row)*N + col);
            } else {
                *reinterpret_cast<uint4*>(&base[OFF_B128 + row*BP + b_off]) = make_uint4(0,0,0,0);
            }
        }
        asm volatile("cp.async.commit_group;");
    };

    load_tile(0, 0);
    if (nt > 1) load_tile(1, 1);
    if (nt > 2) load_tile(2, 2);

    for (int it = 0; it < nt; it++) {
        if (it + 3 < nt) {
            load_tile(it + 3, (it + 3) & 3);
            asm volatile("cp.async.wait_group 3;");
        } else {
            asm volatile("cp.async.wait_group 0;");
        }
        __syncthreads();

        bf16* base = sm + (it & 3)*STG128;
        #pragma unroll
        for (int kt = 0; kt < 2; kt++) {
            int kk = kt * 16;
            uint32_t af[4][4];
            #pragma unroll
            for (int mt = 0; mt < 4; mt++) {
                int r = wm*64 + mt*16 + (lane & 15);
                int c = kk + (lane >> 4)*8;
                ldsm4(af[mt], (uint32_t)__cvta_generic_to_shared(&base[r*AP + c]));
            }
            uint32_t bfr[2][4];
            #pragma unroll
            for (int np = 0; np < 2; np++) {
                int kr = kk + (lane & 15);
                int c  = wn*32 + np*16 + (lane >> 4)*8;
                ldsm4t(bfr[np], (uint32_t)__cvta_generic_to_shared(&base[OFF_B128 + kr*BP + c]));
            }
            #pragma unroll
            for (int mt = 0; mt < 4; mt++)
                #pragma unroll
                for (int nt2 = 0; nt2 < 4; nt2++) {
                    int np = nt2 >> 1, s = (nt2 & 1)*2;
                    mma_bf16(acc[mt][nt2], af[mt], bfr[np][s], bfr[np][s+1]);
                }
        }
        __syncthreads();
    }

    int gr = lane >> 2, gc = (lane & 3)*2;
    #pragma unroll
    for (int mt = 0; mt < 4; mt++) {
        #pragma unroll
        for (int nt2 = 0; nt2 < 4; nt2++) {
            int row0 = m0 + wm*64 + mt*16 + gr;
            int col0 = n0 + wn*32 + nt2*8 + gc;
            if (col0 < N) {
                C[(size_t)row0*N + col0]     = acc[mt][nt2][0];
                C[(size_t)(row0+8)*N + col0] = acc[mt][nt2][2];
            }
            if (col0 + 1 < N) {
                C[(size_t)row0*N + col0+1]     = acc[mt][nt2][1];
                C[(size_t)(row0+8)*N + col0+1] = acc[mt][nt2][3];
            }
        }
    }
}

// ---------------- 64x64 tile, 4-stage pipeline ----------------
#define BP64 72
#define OFF_B64 (64*AP)
#define STG64   (64*AP + 32*BP64)

__global__ __launch_bounds__(256) void gemm64(const bf16* __restrict__ A,
                                              const bf16* __restrict__ W,
                                              const float* __restrict__ bias,
                                              const float* __restrict__ gate,
                                              float* __restrict__ C,
                                              int M, int N, int K,
                                              long wz, long cz) {
    __shared__ bf16 sm[4*STG64];

    W += (size_t)blockIdx.z * wz;
    C += (size_t)blockIdx.z * cz;

    int tid = threadIdx.x;
    int n0 = blockIdx.x * 64, m0 = blockIdx.y * 64;
    int warp = tid >> 5, lane = tid & 31;
    int wm = warp >> 2, wn = warp & 3;

    int a_row = tid >> 2, a_off = (tid & 3) * 8;
    int b_row = tid >> 3, b_off = (tid & 7) * 8;

    float acc[2][2][4];
    #pragma unroll
    for (int i = 0; i < 2; i++)
        #pragma unroll
        for (int j = 0; j < 2; j++)
            #pragma unroll
            for (int v = 0; v < 4; v++) acc[i][j][v] = 0.f;

    int nt = K >> 5;

    auto load_tile = [&](int it, int st) {
        bf16* base = sm + st*STG64;
        cp16(&base[a_row*AP + a_off], A + (size_t)(m0 + a_row)*K + it*32 + a_off);
        int col = n0 + b_off;
        if (col < N) {
            cp16(&base[OFF_B64 + b_row*BP64 + b_off], W + (size_t)(it*32 + b_row)*N + col);
        } else {
            *reinterpret_cast<uint4*>(&base[OFF_B64 + b_row*BP64 + b_off]) = make_uint4(0,0,0,0);
        }
        asm volatile("cp.async.commit_group;");
    };

    load_tile(0, 0);
    load_tile(1, 1);
    load_tile(2, 2);

    for (int it = 0; it < nt; it++) {
        if (it + 3 < nt) {
            load_tile(it + 3, (it + 3) & 3);
            asm volatile("cp.async.wait_group 3;");
        } else {
            asm volatile("cp.async.wait_group 0;");
        }
        __syncthreads();

        bf16* base = sm + (it & 3)*STG64;
        #pragma unroll
        for (int kt = 0; kt < 2; kt++) {
            int kk = kt * 16;
            uint32_t af[2][4];
            #pragma unroll
            for (int mt = 0; mt < 2; mt++) {
                int r = wm*32 + mt*16 + (lane & 15);
                int c = kk + (lane >> 4)*8;
                ldsm4(af[mt], (uint32_t)__cvta_generic_to_shared(&base[r*AP + c]));
            }
            uint32_t bfr[4];
            {
                int kr = kk + (lane & 15);
                int c  = wn*16 + (lane >> 4)*8;
                ldsm4t(bfr, (uint32_t)__cvta_generic_to_shared(&base[OFF_B64 + kr*BP64 + c]));
            }
            #pragma unroll
            for (int mt = 0; mt < 2; mt++)
                #pragma unroll
                for (int nt2 = 0; nt2 < 2; nt2++) {
                    int s = nt2*2;
                    mma_bf16(acc[mt][nt2], af[mt], bfr[s], bfr[s+1]);
                }
        }
        __syncthreads();
    }

    int gr = lane >> 2, gc = (lane & 3)*2;
    #pragma unroll
    for (int mt = 0; mt < 2; mt++) {
        int row0 = m0 + wm*32 + mt*16 + gr;
        int bidx = row0 / LL;
        #pragma unroll
        for (int nt2 = 0; nt2 < 2; nt2++) {
            int col0 = n0 + wn*16 + nt2*8 + gc;
            float b0 = bias ? bias[col0] : 0.f;
            float b1 = bias ? bias[col0+1] : 0.f;
            float v00 = acc[mt][nt2][0] + b0, v01 = acc[mt][nt2][1] + b1;
            float v10 = acc[mt][nt2][2] + b0, v11 = acc[mt][nt2][3] + b1;
            if (col0 < N) {
                if (gate) {
                    float gv0 = gate[bidx*6*DM + col0];
                    float gv1 = gate[bidx*6*DM + col0 + 1];
                    C[(size_t)row0*N + col0]       += gv0 * v00;
                    C[(size_t)row0*N + col0+1]     += gv1 * v01;
                    C[(size_t)(row0+8)*N + col0]   += gv0 * v10;
                    C[(size_t)(row0+8)*N + col0+1] += gv1 * v11;
                } else {
                    C[(size_t)row0*N + col0]       = v00;
                    C[(size_t)row0*N + col0+1]     = v01;
                    C[(size_t)(row0+8)*N + col0]   = v10;
                    C[(size_t)(row0+8)*N + col0+1] = v11;
                }
            }
        }
    }
}

// ---------------- pre-norm + AdaLN modulation ----------------
__global__ void k_prenorm_mod(int l, const float* __restrict__ hs,
                              const float* __restrict__ norm_w) {
    int t = blockIdx.x;
    int b = t / LL;
    const float* aff = &g_aff[(l*BB + b)*6*DM];
    float vals[3];
    float ss = 0.f;
    #pragma unroll
    for (int i = 0; i < 3; i++) {
        int d = threadIdx.x + i*256;
        float v = (l == 0) ? hs[t*DM + d]
                           : (g_resid[t*DM + d] + g_hidden[t*DM + d]);
        g_resid[t*DM + d] = v;
        vals[i] = v;
        ss += v*v;
    }
    ss = block_reduce_sum(ss);
    float rstd = rsqrtf(ss * (1.f/DM) + 1e-5f);
    #pragma unroll
    for (int i = 0; i < 3; i++) {
        int d = threadIdx.x + i*256;
        float x = vals[i] * rstd * norm_w[l*DM + d];
        g_hidden[t*DM + d] = x;
        g_u_bf[t*DM + d] = __float2bfloat16(x * (1.f + aff[DM + d]) + aff[d]);
    }
}

// ---------------- conv: sliding window over t ----------------
// grid (BB*7*8): b = z/56... encode: blockIdx.x = ((b*7 + part)*8 + zt)
__global__ __launch_bounds__(256) void k_conv(int l, const float* __restrict__ conv_w,
                                              const float* __restrict__ conv_b) {
    int bi = blockIdx.x;
    int zt = bi & 7;            // t strip 0..7
    int part = (bi >> 3) % 7;   // channel group
    int b = bi / 56;
    int c = part*256 + threadIdx.x;    // < 1792
    int t0 = zt * 64;

    const float* wc = conv_w + (size_t)(l*CONVD + c)*4;
    float w0 = wc[0], w1 = wc[1], w2 = wc[2], w3 = wc[3];
    float bias = conv_b[l*CONVD + c];

    const float* src = g_zx + (size_t)b*LL*DIP + DI + c;
    float* dst = g_xBC + (size_t)b*LL*CONVD + c;

    float x0 = (t0 >= 3) ? src[(size_t)(t0-3)*DIP] : 0.f;
    float x1 = (t0 >= 2) ? src[(size_t)(t0-2)*DIP] : 0.f;
    float x2 = (t0 >= 1) ? src[(size_t)(t0-1)*DIP] : 0.f;

    for (int tt = 0; tt < 64; tt += 8) {
        float v[8];
        #pragma unroll
        for (int j = 0; j < 8; j++)
            v[j] = src[(size_t)(t0 + tt + j)*DIP];
        #pragma unroll
        for (int j = 0; j < 8; j++) {
            float y = bias + w0*x0 + w1*x1 + w2*x2 + w3*v[j];
            dst[(size_t)(t0 + tt + j)*CONVD] = siluf(y);
            x0 = x1; x1 = x2; x2 = v[j];
        }
    }
}

// ---------------- dt/dA ----------------
__global__ void k_dt(int l, const float* __restrict__ dt_bias,
                     const float* __restrict__ A_log) {
    int i = blockIdx.x * 256 + threadIdx.x;
    if (i >= BB*LL*NH) return;
    int hh = i % NH;
    float x = g_zx[(size_t)(i / NH)*DIP + DI + CONVD + hh] + dt_bias[l*NH + hh];
    float dt = (x > 20.f) ? x : log1pf(expf(x));
    g_dt[i] = dt;
    g_dA[i] = expf(-expf(A_log[l*NH + hh]) * dt);
}

// ---------------- SSM scan (TCH=16) ----------------
#define TCH 16
__global__ __launch_bounds__(256) void k_scan(int l, const float* __restrict__ D_ssm) {
    int bh = blockIdx.x;
    int b = bh / NH, hh = bh % NH;
    int ps = blockIdx.y;
    int tid = threadIdx.x;
    int pl = tid >> 3;
    int ng = tid & 7;
    int nb = ng * 16;
    float hreg[16];
    #pragma unroll
    for (int i = 0; i < 16; i++) hreg[i] = 0.f;

    __shared__ float sx[TCH][32];
    __shared__ float sB[TCH][DSTATE];
    __shared__ float sC[TCH][DSTATE];
    __shared__ float sdt[TCH], sdA[TCH];
    float Dh = D_ssm[l*NH + hh];

    for (int t0 = 0; t0 < LL; t0 += TCH) {
        #pragma unroll
        for (int st = 0; st < TCH; st++) {
            const float* xb = g_xBC + (size_t)(b*LL + t0 + st)*CONVD;
            if (tid < 32)       sx[st][tid]      = xb[hh*HD + ps*32 + tid];
            else if (tid < 160) sB[st][tid-32]   = xb[DI + tid - 32];
            else                sC[st][tid-160]  = xb[DI + DSTATE + tid - 160];
            if (tid < 32)       sC[st][96+tid]   = xb[DI + DSTATE + 96 + tid];
        }
        if (tid < TCH) {
            int tok = b*LL + t0 + tid;
            sdt[tid] = g_dt[tok*NH + hh];
            sdA[tid] = g_dA[tok*NH + hh];
        }
        __syncthreads();
        #pragma unroll
        for (int st = 0; st < TCH; st++) {
            float dtt = sdt[st], dAt = sdA[st];
            float xp  = sx[st][pl];
            float dbx = dtt * xp;
            float y = 0.f;
            #pragma unroll
            for (int i = 0; i < 16; i++) {
                float hv = hreg[i]*dAt + dbx*sB[st][nb+i];
                hreg[i] = hv;
                y += hv * sC[st][nb+i];
            }
            y += __shfl_xor_sync(0xffffffffu, y, 1);
            y += __shfl_xor_sync(0xffffffffu, y, 2);
            y += __shfl_xor_sync(0xffffffffu, y, 4);
            if (ng == 0) {
                int tok = b*LL + t0 + st;
                g_y[(size_t)tok*DI + hh*HD + ps*32 + pl] = y + xp * Dh;
            }
        }
        __syncthreads();
    }
}

// ---------------- gated RMS norm -> y bf16 ----------------
__global__ void k_gatenorm(int l, const float* __restrict__ ssm_norm_w) {
    int t = blockIdx.x;
    __shared__ float sv[DI];
    float ss = 0.f;
    for (int d = threadIdx.x; d < DI; d += 256) {
        float z = g_zx[(size_t)t*DIP + d];
        float v = g_y[(size_t)t*DI + d] * siluf(z);
        sv[d] = v;
        ss += v*v;
    }
    ss = block_reduce_sum(ss);
    float rstd = rsqrtf(ss * (1.f/DI) + 1e-5f);
    for (int d = threadIdx.x; d < DI; d += 256)
        g_y_bf[(size_t)t*DI + d] = __float2bfloat16(sv[d] * rstd * ssm_norm_w[l*DI + d]);
}

// ---------------- u = ln_noaffine(hidden)*(1+sc_msa)+sh_msa ----------------
__global__ void k_post_mamba(int l) {
    int t = blockIdx.x;
    int b = t / LL;
    const float* aff = &g_aff[(l*BB + b)*6*DM];
    float vals[3];
    float s1 = 0.f;
    #pragma unroll
    for (int i = 0; i < 3; i++) {
        int d = threadIdx.x + i*256;
        float v = g_hidden[t*DM + d];
        vals[i] = v;
        s1 += v;
    }
    s1 = block_reduce_sum(s1);
    float mean = s1 * (1.f/DM);
    float s2 = 0.f;
    #pragma unroll
    for (int i = 0; i < 3; i++) { float c = vals[i] - mean; s2 += c*c; }
    s2 = block_reduce_sum(s2);
    float rstd = rsqrtf(s2 * (1.f/DM) + 1e-6f);
    #pragma unroll
    for (int i = 0; i < 3; i++) {
        int d = threadIdx.x + i*256;
        float x = (vals[i] - mean) * rstd;
        g_u_bf[t*DM + d] = __float2bfloat16(x * (1.f + aff[4*DM + d]) + aff[3*DM + d]);
    }
}

// ---------------- cross attention ----------------
__global__ __launch_bounds__(512) void k_attn(int l) {
    int qt = blockIdx.x, hh = blockIdx.y, b = blockIdx.z;
    int warp = threadIdx.x >> 5, lane = threadIdx.x & 31;
    const float* kp = g_kall + (size_t)l*BB*LCC*AINNER;
    const float* vp = g_vall + (size_t)l*BB*LCC*AINNER;
    __shared__ float Ks[64][65];
    __shared__ float Vs[64][64];
    __shared__ float Qs[16][64];
    __shared__ float Ps[16][64];
    for (int idx = threadIdx.x; idx < 64*64; idx += 512) {
        int m = idx >> 6, d = idx & 63;
        Ks[m][d] = kp[(size_t)(b*LCC + m)*AINNER + hh*ADD + d];
        Vs[m][d] = vp[(size_t)(b*LCC + m)*AINNER + hh*ADD + d];
    }
    for (int idx = threadIdx.x; idx < 16*64; idx += 512) {
        int q = idx >> 6, d = idx & 63;
        Qs[q][d] = g_q[(size_t)(b*LL + qt*16 + q)*AINNER + hh*ADD + d];
    }
    __syncthreads();
    int q = warp;
    float s0 = 0.f, s1 = 0.f;
    #pragma unroll 8
    for (int d = 0; d < 64; d++) {
        float qd = Qs[q][d];
        s0 += qd * Ks[lane][d];
        s1 += qd * Ks[lane+32][d];
    }
    s0 *= 0.125f; s1 *= 0.125f;
    float mx = fmaxf(s0, s1);
    #pragma unroll
    for (int o = 16; o > 0; o >>= 1) mx = fmaxf(mx, __shfl_xor_sync(0xffffffffu, mx, o));
    float e0 = expf(s0 - mx), e1 = expf(s1 - mx);
    float sum = e0 + e1;
    #pragma unroll
    for (int o = 16; o > 0; o >>= 1) sum += __shfl_xor_sync(0xffffffffu, sum, o);
    float inv = 1.f / sum;
    Ps[q][lane] = e0 * inv;
    Ps[q][lane+32] = e1 * inv;
    __syncwarp();
    float o0 = 0.f, o1 = 0.f;
    #pragma unroll 8
    for (int m = 0; m < 64; m++) {
        float pm = Ps[q][m];
        o0 += pm * Vs[m][lane];
        o1 += pm * Vs[m][lane+32];
    }
    size_t base = (size_t)(b*LL + qt*16 + q)*AINNER + hh*ADD;
    g_ao_bf[base + lane]      = __float2bfloat16(o0);
    g_ao_bf[base + lane + 32] = __float2bfloat16(o1);
}

// ---------------- final rmsnorm ----------------
__global__ void k_final(const float* __restrict__ norm_f_w, float* __restrict__ out) {
    int t = blockIdx.x;
    float vals[3];
    float ss = 0.f;
    #pragma unroll
    for (int i = 0; i < 3; i++) {
        int d = threadIdx.x + i*256;
        float v = g_hidden[t*DM + d] + g_resid[t*DM + d];
        vals[i] = v;
        ss += v*v;
    }
    ss = block_reduce_sum(ss);
    float rstd = rsqrtf(ss * (1.f/DM) + 1e-5f);
    #pragma unroll
    for (int i = 0; i < 3; i++) {
        int d = threadIdx.x + i*256;
        out[t*DM + d] = vals[i] * rstd * norm_f_w[d];
    }
}

// ---------------- host ----------------
#define GETSYM(p, T, s) do { void* tmp_; cudaGetSymbolAddress(&tmp_, s); p = (T*)tmp_; } while(0)

extern "C" void kernel_launch(void* const* d_in, const int* in_sizes, int n_in,
                              void* d_out, int out_size) {
    const float* hs        = (const float*)d_in[0];
    const float* ref       = (const float*)d_in[1];
    const float* norm_w    = (const float*)d_in[2];
    const float* ada_w     = (const float*)d_in[3];
    const float* ada_b     = (const float*)d_in[4];
    const float* in_w      = (const float*)d_in[5];
    const float* conv_w    = (const float*)d_in[6];
    const float* conv_b    = (const float*)d_in[7];
    const float* dt_bias   = (const float*)d_in[8];
    const float* A_log     = (const float*)d_in[9];
    const float* D_ssm     = (const float*)d_in[10];
    const float* ssm_nw    = (const float*)d_in[11];
    const float* out_w     = (const float*)d_in[12];
    const float* out_b     = (const float*)d_in[13];
    const float* q_w       = (const float*)d_in[14];
    const float* k_w       = (const float*)d_in[15];
    const float* v_w       = (const float*)d_in[16];
    const float* o_w       = (const float*)d_in[17];
    const float* o_b       = (const float*)d_in[18];
    const float* norm_f_w  = (const float*)d_in[19];
    float* out = (float*)d_out;

    static int init_done = 0;
    static cudaStream_t s2;
    static cudaEvent_t ev_fork, ev_join;
    if (!init_done) {
        cudaFuncSetAttribute(gemm128, cudaFuncAttributeMaxDynamicSharedMemorySize, SM128_BYTES);
        cudaStreamCreateWithFlags(&s2, cudaStreamNonBlocking);
        cudaEventCreateWithFlags(&ev_fork, cudaEventDisableTiming);
        cudaEventCreateWithFlags(&ev_join, cudaEventDisableTiming);
        init_done = 1;
    }

    float *p_zx, *p_q, *p_y, *p_kall, *p_vall, *p_hidden, *p_aff;
    GETSYM(p_zx,    float, g_zx);
    GETSYM(p_q,     float, g_q);
    GETSYM(p_y,     float, g_y);
    GETSYM(p_kall,  float, g_kall);
    GETSYM(p_vall,  float, g_vall);
    GETSYM(p_hidden,float, g_hidden);
    GETSYM(p_aff,   float, g_aff);

    bf16 *u_bf,*y_bf,*ao_bf,*ref_bf,*wi_bf,*wo_bf,*wq_bf,*wk_bf,*wv_bf,*wp_bf;
    GETSYM(u_bf,  bf16, g_u_bf);
    GETSYM(y_bf,  bf16, g_y_bf);
    GETSYM(ao_bf, bf16, g_ao_bf);
    GETSYM(ref_bf,bf16, g_ref_bf);
    GETSYM(wi_bf, bf16, g_wi_bf);
    GETSYM(wo_bf, bf16, g_wo_bf);
    GETSYM(wq_bf, bf16, g_wq_bf);
    GETSYM(wk_bf, bf16, g_wk_bf);
    GETSYM(wv_bf, bf16, g_wv_bf);
    GETSYM(wp_bf, bf16, g_wp_bf);

    const int M = BB*LL;   // 1024
    #define CVT(src, dst, n)    k_tobf16<<<((n)+255)/256, 256>>>(src, dst, n)
    #define CVT2(src, dst, n)   k_tobf16<<<((n)+255)/256, 256, 0, s2>>>(src, dst, n)

    // main stream: things layer-0 needs immediately
    k_condsilu<<<(BB*DM + 255)/256, 256>>>(ref);
    k_ada<<<(NLAYER*BB*6*DM + 255)/256, 256>>>(ada_w, ada_b);
    CVT(in_w, wi_bf, NLAYER*DM*DIP);

    // fork side stream: attention-path weights + kv projections
    cudaEventRecord(ev_fork, 0);
    cudaStreamWaitEvent(s2, ev_fork, 0);
    CVT2(ref, ref_bf, BB*LCC*DM);
    CVT2(k_w, wk_bf, NLAYER*DM*AINNER);
    CVT2(v_w, wv_bf, NLAYER*DM*AINNER);
    CVT2(out_w, wo_bf, NLAYER*DI*DM);
    CVT2(q_w,   wq_bf, NLAYER*DM*AINNER);
    CVT2(o_w,   wp_bf, NLAYER*AINNER*DM);
    gemm128<<<dim3(AINNER/128, (BB*LCC)/128, NLAYER), 256, SM128_BYTES, s2>>>(ref_bf, wk_bf,
        p_kall, BB*LCC, AINNER, DM, (long)DM*AINNER, (long)BB*LCC*AINNER);
    gemm128<<<dim3(AINNER/128, (BB*LCC)/128, NLAYER), 256, SM128_BYTES, s2>>>(ref_bf, wv_bf,
        p_vall, BB*LCC, AINNER, DM, (long)DM*AINNER, (long)BB*LCC*AINNER);
    cudaEventRecord(ev_join, s2);

    for (int l = 0; l < NLAYER; l++) {
        k_prenorm_mod<<<M, 256>>>(l, hs, norm_w);
        gemm128<<<dim3((DIP+127)/128, M/128), 256, SM128_BYTES>>>(u_bf,
            wi_bf + (size_t)l*DM*DIP, p_zx, M, DIP, DM, 0, 0);
        k_conv<<<BB*7*8, 256>>>(l, conv_w, conv_b);
        k_dt<<<(BB*LL*NH + 255)/256, 256>>>(l, dt_bias, A_log);
        k_scan<<<dim3(BB*NH, 2), 256>>>(l, D_ssm);
        k_gatenorm<<<M, 256>>>(l, ssm_nw);
        if (l == 0) cudaStreamWaitEvent(0, ev_join, 0);   // join side stream
        gemm64<<<dim3(DM/64, M/64), 256>>>(y_bf, wo_bf + (size_t)l*DI*DM, out_b + l*DM,
            p_aff + (size_t)(l*BB)*6*DM + 2*DM, p_hidden, M, DM, DI, 0, 0);
        k_post_mamba<<<M, 256>>>(l);
        gemm64<<<dim3(AINNER/64, M/64), 256>>>(u_bf, wq_bf + (size_t)l*DM*AINNER, nullptr,
            nullptr, p_q, M, AINNER, DM, 0, 0);
        k_attn<<<dim3(LL/16, AHH, BB), 512>>>(l);
        gemm64<<<dim3(DM/64, M/64), 256>>>(ao_bf, wp_bf + (size_t)l*AINNER*DM, o_b + l*DM,
            p_aff + (size_t)(l*BB)*6*DM + 5*DM, p_hidden, M, DM, AINNER, 0, 0);
    }
    k_final<<<M, 256>>>(norm_f_w, out);
}

// round 15
// speedup vs baseline: 1.0808x; 1.0808x over previous
#include <cuda_runtime.h>
#include <cuda_bf16.h>
#include <math.h>
#include <stdint.h>

#define BB 2
#define LL 512
#define LCC 64
#define DM 768
#define DI 1536
#define NH 24
#define HD 64
#define DSTATE 128
#define CONVD 1792
#define DIP 3352
#define NLAYER 8
#define AHH 8
#define ADD 64
#define AINNER 512

typedef __nv_bfloat16 bf16;

// ---------------- scratch ----------------
__device__ float g_hidden[BB*LL*DM];
__device__ float g_resid [BB*LL*DM];
__device__ float g_zx    [BB*LL*DIP];
__device__ float g_xBC   [BB*LL*CONVD];
__device__ float g_dt    [BB*LL*NH];
__device__ float g_dA    [BB*LL*NH];
__device__ float g_y     [BB*LL*DI];
__device__ float g_q     [BB*LL*AINNER];
__device__ float g_kall  [NLAYER*BB*LCC*AINNER];
__device__ float g_vall  [NLAYER*BB*LCC*AINNER];
__device__ float g_aff   [NLAYER*BB*6*DM];
__device__ float g_csilu [BB*DM];

__device__ bf16 g_u_bf [BB*LL*DM];
__device__ bf16 g_y_bf [BB*LL*DI];
__device__ bf16 g_ao_bf[BB*LL*AINNER];
__device__ bf16 g_ref_bf[BB*LCC*DM];

__device__ bf16 g_wi_bf[NLAYER*DM*DIP];
__device__ bf16 g_wo_bf[NLAYER*DI*DM];
__device__ bf16 g_wq_bf[NLAYER*DM*AINNER];
__device__ bf16 g_wk_bf[NLAYER*DM*AINNER];
__device__ bf16 g_wv_bf[NLAYER*DM*AINNER];
__device__ bf16 g_wp_bf[NLAYER*AINNER*DM];

__device__ __forceinline__ float siluf(float x) { return x / (1.f + expf(-x)); }

__device__ __forceinline__ float block_reduce_sum(float v) {
    __shared__ float red_s[33];
    int lane = threadIdx.x & 31;
    int wid  = threadIdx.x >> 5;
    #pragma unroll
    for (int o = 16; o > 0; o >>= 1) v += __shfl_xor_sync(0xffffffffu, v, o);
    if (lane == 0) red_s[wid] = v;
    __syncthreads();
    int nw = (blockDim.x + 31) >> 5;
    if (wid == 0) {
        float x = (lane < nw) ? red_s[lane] : 0.f;
        #pragma unroll
        for (int o = 16; o > 0; o >>= 1) x += __shfl_xor_sync(0xffffffffu, x, o);
        if (lane == 0) red_s[32] = x;
    }
    __syncthreads();
    float r = red_s[32];
    __syncthreads();
    return r;
}

__global__ void k_tobf16(const float* __restrict__ src, bf16* __restrict__ dst, int n) {
    int i = blockIdx.x * 256 + threadIdx.x;
    if (i < n) dst[i] = __float2bfloat16(src[i]);
}

__global__ void k_condsilu(const float* __restrict__ ref) {
    int i = blockIdx.x * 256 + threadIdx.x;
    if (i >= BB*DM) return;
    int b = i / DM, d = i % DM;
    float s = 0.f;
    for (int m = 0; m < LCC; m++) s += ref[(b*LCC + m)*DM + d];
    s *= (1.f / LCC);
    g_csilu[i] = siluf(s);
}

__global__ void k_ada(const float* __restrict__ ada_w, const float* __restrict__ ada_b) {
    int i = blockIdx.x * 256 + threadIdx.x;
    if (i >= NLAYER*BB*6*DM) return;
    int j  = i % (6*DM);
    int lb = i / (6*DM);
    int b  = lb % BB;
    int l  = lb / BB;
    float s = ada_b[l*6*DM + j];
    const float* cs = &g_csilu[b*DM];
    const float* w  = ada_w + (size_t)l*DM*6*DM + j;
    for (int d = 0; d < DM; d++) s += cs[d] * w[(size_t)d*6*DM];
    g_aff[i] = s;
}

// ================= bf16 tensor-core GEMM =================
__device__ __forceinline__ void ldsm4(uint32_t* r, uint32_t addr) {
    asm volatile("ldmatrix.sync.aligned.m8n8.x4.shared.b16 {%0,%1,%2,%3}, [%4];"
        : "=r"(r[0]), "=r"(r[1]), "=r"(r[2]), "=r"(r[3]) : "r"(addr));
}
__device__ __forceinline__ void ldsm4t(uint32_t* r, uint32_t addr) {
    asm volatile("ldmatrix.sync.aligned.m8n8.x4.trans.shared.b16 {%0,%1,%2,%3}, [%4];"
        : "=r"(r[0]), "=r"(r[1]), "=r"(r[2]), "=r"(r[3]) : "r"(addr));
}
__device__ __forceinline__ void mma_bf16(float* d, const uint32_t* a, uint32_t b0, uint32_t b1) {
    asm volatile("mma.sync.aligned.m16n8k16.row.col.f32.bf16.bf16.f32 "
        "{%0,%1,%2,%3}, {%4,%5,%6,%7}, {%8,%9}, {%0,%1,%2,%3};"
        : "+f"(d[0]), "+f"(d[1]), "+f"(d[2]), "+f"(d[3])
        : "r"(a[0]), "r"(a[1]), "r"(a[2]), "r"(a[3]), "r"(b0), "r"(b1));
}
__device__ __forceinline__ void cp16(void* smem, const void* gmem) {
    uint32_t s = (uint32_t)__cvta_generic_to_shared(smem);
    asm volatile("cp.async.cg.shared.global [%0], [%1], 16;" :: "r"(s), "l"(gmem));
}

#define AP 40    // A smem pitch (bf16)
#define BP 136   // B smem pitch (bf16)

// ---------------- 128x128 tile, 3-stage pipeline, 2 CTAs/SM, z-batched ----------------
#define OFF_B128 (128*AP)
#define STG128   (128*AP + 32*BP)
#define SM128_BYTES (3*STG128*2)   // 56832

__global__ __launch_bounds__(256, 2) void gemm128(const bf16* __restrict__ A,
                                                  const bf16* __restrict__ W,
                                                  float* __restrict__ C,
                                                  int M, int N, int K,
                                                  long wz, long cz) {
    extern __shared__ bf16 sm[];
    W += (size_t)blockIdx.z * wz;
    C += (size_t)blockIdx.z * cz;

    int tid = threadIdx.x;
    int n0 = blockIdx.x * 128, m0 = blockIdx.y * 128;
    int warp = tid >> 5, lane = tid & 31;
    int wm = warp >> 2, wn = warp & 3;

    int a_row = tid >> 1, a_off = (tid & 1) * 16;
    int b_row0 = tid >> 4, b_off = (tid & 15) * 8;

    float acc[4][4][4];
    #pragma unroll
    for (int i = 0; i < 4; i++)
        #pragma unroll
        for (int j = 0; j < 4; j++)
            #pragma unroll
            for (int v = 0; v < 4; v++) acc[i][j][v] = 0.f;

    int nt = K >> 5;

    auto load_tile = [&](int it, int st) {
        bf16* base = sm + st*STG128;
        const bf16* src = A + (size_t)(m0 + a_row)*K + it*32 + a_off;
        cp16(&base[a_row*AP + a_off],     src);
        cp16(&base[a_row*AP + a_off + 8], src + 8);
        #pragma unroll
        for (int s = 0; s < 2; s++) {
            int row = b_row0 + s*16;
            int col = n0 + b_off;
            if (col < N) {
                cp16(&base[OFF_B128 + row*BP + b_off], W + (size_t)(it*32 + row)*N + col);
            } else {
                *reinterpret_cast<uint4*>(&base[OFF_B128 + row*BP + b_off]) = make_uint4(0,0,0,0);
            }
        }
        asm volatile("cp.async.commit_group;");
    };

    load_tile(0, 0);
    load_tile(1, 1);

    int st = 0, st_next = 2;
    for (int it = 0; it < nt; it++) {
        if (it + 2 < nt) {
            load_tile(it + 2, st_next);
            asm volatile("cp.async.wait_group 2;");
        } else {
            asm volatile("cp.async.wait_group 0;");
        }
        __syncthreads();

        bf16* base = sm + st*STG128;
        #pragma unroll
        for (int kt = 0; kt < 2; kt++) {
            int kk = kt * 16;
            uint32_t af[4][4];
            #pragma unroll
            for (int mt = 0; mt < 4; mt++) {
                int r = wm*64 + mt*16 + (lane & 15);
                int c = kk + (lane >> 4)*8;
                ldsm4(af[mt], (uint32_t)__cvta_generic_to_shared(&base[r*AP + c]));
            }
            uint32_t bfr[2][4];
            #pragma unroll
            for (int np = 0; np < 2; np++) {
                int kr = kk + (lane & 15);
                int c  = wn*32 + np*16 + (lane >> 4)*8;
                ldsm4t(bfr[np], (uint32_t)__cvta_generic_to_shared(&base[OFF_B128 + kr*BP + c]));
            }
            #pragma unroll
            for (int mt = 0; mt < 4; mt++)
                #pragma unroll
                for (int nt2 = 0; nt2 < 4; nt2++) {
                    int np = nt2 >> 1, s = (nt2 & 1)*2;
                    mma_bf16(acc[mt][nt2], af[mt], bfr[np][s], bfr[np][s+1]);
                }
        }
        __syncthreads();
        st = (st == 2) ? 0 : st + 1;
        st_next = (st_next == 2) ? 0 : st_next + 1;
    }

    int gr = lane >> 2, gc = (lane & 3)*2;
    #pragma unroll
    for (int mt = 0; mt < 4; mt++) {
        #pragma unroll
        for (int nt2 = 0; nt2 < 4; nt2++) {
            int row0 = m0 + wm*64 + mt*16 + gr;
            int col0 = n0 + wn*32 + nt2*8 + gc;
            if (col0 < N) {
                C[(size_t)row0*N + col0]     = acc[mt][nt2][0];
                C[(size_t)(row0+8)*N + col0] = acc[mt][nt2][2];
            }
            if (col0 + 1 < N) {
                C[(size_t)row0*N + col0+1]     = acc[mt][nt2][1];
                C[(size_t)(row0+8)*N + col0+1] = acc[mt][nt2][3];
            }
        }
    }
}

// ---------------- 64x64 tile (small GEMMs), 4-stage pipeline ----------------
#define BP64 72
#define OFF_B64 (64*AP)
#define STG64   (64*AP + 32*BP64)

__global__ __launch_bounds__(256) void gemm64(const bf16* __restrict__ A,
                                              const bf16* __restrict__ W,
                                              const float* __restrict__ bias,
                                              const float* __restrict__ gate,
                                              float* __restrict__ C,
                                              int M, int N, int K,
                                              long wz, long cz) {
    __shared__ bf16 sm[4*STG64];

    W += (size_t)blockIdx.z * wz;
    C += (size_t)blockIdx.z * cz;

    int tid = threadIdx.x;
    int n0 = blockIdx.x * 64, m0 = blockIdx.y * 64;
    int warp = tid >> 5, lane = tid & 31;
    int wm = warp >> 2, wn = warp & 3;

    int a_row = tid >> 2, a_off = (tid & 3) * 8;
    int b_row = tid >> 3, b_off = (tid & 7) * 8;

    float acc[2][2][4];
    #pragma unroll
    for (int i = 0; i < 2; i++)
        #pragma unroll
        for (int j = 0; j < 2; j++)
            #pragma unroll
            for (int v = 0; v < 4; v++) acc[i][j][v] = 0.f;

    int nt = K >> 5;

    auto load_tile = [&](int it, int st) {
        bf16* base = sm + st*STG64;
        cp16(&base[a_row*AP + a_off], A + (size_t)(m0 + a_row)*K + it*32 + a_off);
        int col = n0 + b_off;
        if (col < N) {
            cp16(&base[OFF_B64 + b_row*BP64 + b_off], W + (size_t)(it*32 + b_row)*N + col);
        } else {
            *reinterpret_cast<uint4*>(&base[OFF_B64 + b_row*BP64 + b_off]) = make_uint4(0,0,0,0);
        }
        asm volatile("cp.async.commit_group;");
    };

    load_tile(0, 0);
    load_tile(1, 1);
    load_tile(2, 2);

    for (int it = 0; it < nt; it++) {
        if (it + 3 < nt) {
            load_tile(it + 3, (it + 3) & 3);
            asm volatile("cp.async.wait_group 3;");
        } else {
            asm volatile("cp.async.wait_group 0;");
        }
        __syncthreads();

        bf16* base = sm + (it & 3)*STG64;
        #pragma unroll
        for (int kt = 0; kt < 2; kt++) {
            int kk = kt * 16;
            uint32_t af[2][4];
            #pragma unroll
            for (int mt = 0; mt < 2; mt++) {
                int r = wm*32 + mt*16 + (lane & 15);
                int c = kk + (lane >> 4)*8;
                ldsm4(af[mt], (uint32_t)__cvta_generic_to_shared(&base[r*AP + c]));
            }
            uint32_t bfr[4];
            {
                int kr = kk + (lane & 15);
                int c  = wn*16 + (lane >> 4)*8;
                ldsm4t(bfr, (uint32_t)__cvta_generic_to_shared(&base[OFF_B64 + kr*BP64 + c]));
            }
            #pragma unroll
            for (int mt = 0; mt < 2; mt++)
                #pragma unroll
                for (int nt2 = 0; nt2 < 2; nt2++) {
                    int s = nt2*2;
                    mma_bf16(acc[mt][nt2], af[mt], bfr[s], bfr[s+1]);
                }
        }
        __syncthreads();
    }

    int gr = lane >> 2, gc = (lane & 3)*2;
    #pragma unroll
    for (int mt = 0; mt < 2; mt++) {
        int row0 = m0 + wm*32 + mt*16 + gr;
        int bidx = row0 / LL;
        #pragma unroll
        for (int nt2 = 0; nt2 < 2; nt2++) {
            int col0 = n0 + wn*16 + nt2*8 + gc;
            float b0 = bias ? bias[col0] : 0.f;
            float b1 = bias ? bias[col0+1] : 0.f;
            float v00 = acc[mt][nt2][0] + b0, v01 = acc[mt][nt2][1] + b1;
            float v10 = acc[mt][nt2][2] + b0, v11 = acc[mt][nt2][3] + b1;
            if (col0 < N) {
                if (gate) {
                    float gv0 = gate[bidx*6*DM + col0];
                    float gv1 = gate[bidx*6*DM + col0 + 1];
                    C[(size_t)row0*N + col0]       += gv0 * v00;
                    C[(size_t)row0*N + col0+1]     += gv1 * v01;
                    C[(size_t)(row0+8)*N + col0]   += gv0 * v10;
                    C[(size_t)(row0+8)*N + col0+1] += gv1 * v11;
                } else {
                    C[(size_t)row0*N + col0]       = v00;
                    C[(size_t)row0*N + col0+1]     = v01;
                    C[(size_t)(row0+8)*N + col0]   = v10;
                    C[(size_t)(row0+8)*N + col0+1] = v11;
                }
            }
        }
    }
}

// ---------------- pre-norm + AdaLN modulation (l==0 reads hs) ----------------
__global__ void k_prenorm_mod(int l, const float* __restrict__ hs,
                              const float* __restrict__ norm_w) {
    int t = blockIdx.x;
    int b = t / LL;
    const float* aff = &g_aff[(l*BB + b)*6*DM];
    float vals[3];
    float ss = 0.f;
    #pragma unroll
    for (int i = 0; i < 3; i++) {
        int d = threadIdx.x + i*256;
        float v = (l == 0) ? hs[t*DM + d]
                           : (g_resid[t*DM + d] + g_hidden[t*DM + d]);
        g_resid[t*DM + d] = v;
        vals[i] = v;
        ss += v*v;
    }
    ss = block_reduce_sum(ss);
    float rstd = rsqrtf(ss * (1.f/DM) + 1e-5f);
    #pragma unroll
    for (int i = 0; i < 3; i++) {
        int d = threadIdx.x + i*256;
        float x = vals[i] * rstd * norm_w[l*DM + d];
        g_hidden[t*DM + d] = x;
        g_u_bf[t*DM + d] = __float2bfloat16(x * (1.f + aff[DM + d]) + aff[d]);
    }
}

// ---------------- conv: sliding window over t (single pass over g_zx) ----------------
// blockIdx.x = ((b*7 + part)*8 + zt); thread owns one channel for a 64-token strip
__global__ __launch_bounds__(256) void k_conv(int l, const float* __restrict__ conv_w,
                                              const float* __restrict__ conv_b) {
    int bi = blockIdx.x;
    int zt = bi & 7;
    int part = (bi >> 3) % 7;
    int b = bi / 56;
    int c = part*256 + threadIdx.x;
    int t0 = zt * 64;

    const float* wc = conv_w + (size_t)(l*CONVD + c)*4;
    float w0 = wc[0], w1 = wc[1], w2 = wc[2], w3 = wc[3];
    float bias = conv_b[l*CONVD + c];

    const float* src = g_zx + (size_t)b*LL*DIP + DI + c;
    float* dst = g_xBC + (size_t)b*LL*CONVD + c;

    float x0 = (t0 >= 3) ? src[(size_t)(t0-3)*DIP] : 0.f;
    float x1 = (t0 >= 2) ? src[(size_t)(t0-2)*DIP] : 0.f;
    float x2 = (t0 >= 1) ? src[(size_t)(t0-1)*DIP] : 0.f;

    for (int tt = 0; tt < 64; tt += 8) {
        float v[8];
        #pragma unroll
        for (int j = 0; j < 8; j++)
            v[j] = src[(size_t)(t0 + tt + j)*DIP];
        #pragma unroll
        for (int j = 0; j < 8; j++) {
            float y = bias + w0*x0 + w1*x1 + w2*x2 + w3*v[j];
            dst[(size_t)(t0 + tt + j)*CONVD] = siluf(y);
            x0 = x1; x1 = x2; x2 = v[j];
        }
    }
}

// ---------------- dt/dA ----------------
__global__ void k_dt(int l, const float* __restrict__ dt_bias,
                     const float* __restrict__ A_log) {
    int i = blockIdx.x * 256 + threadIdx.x;
    if (i >= BB*LL*NH) return;
    int hh = i % NH;
    float x = g_zx[(size_t)(i / NH)*DIP + DI + CONVD + hh] + dt_bias[l*NH + hh];
    float dt = (x > 20.f) ? x : log1pf(expf(x));
    g_dt[i] = dt;
    g_dA[i] = expf(-expf(A_log[l*NH + hh]) * dt);
}

// ---------------- SSM scan (TCH=8, div-free loads) ----------------
#define TCH 8
__global__ __launch_bounds__(256) void k_scan(int l, const float* __restrict__ D_ssm) {
    int bh = blockIdx.x;
    int b = bh / NH, hh = bh % NH;
    int ps = blockIdx.y;
    int tid = threadIdx.x;
    int pl = tid >> 3;
    int ng = tid & 7;
    int nb = ng * 16;
    float hreg[16];
    #pragma unroll
    for (int i = 0; i < 16; i++) hreg[i] = 0.f;

    __shared__ float sx[TCH][32];
    __shared__ float sB[TCH][DSTATE];
    __shared__ float sC[TCH][DSTATE];
    __shared__ float sdt[TCH], sdA[TCH];
    float Dh = D_ssm[l*NH + hh];

    for (int t0 = 0; t0 < LL; t0 += TCH) {
        #pragma unroll
        for (int st = 0; st < TCH; st++) {
            const float* xb = g_xBC + (size_t)(b*LL + t0 + st)*CONVD;
            if (tid < 32)       sx[st][tid]      = xb[hh*HD + ps*32 + tid];
            else if (tid < 160) sB[st][tid-32]   = xb[DI + tid - 32];
            else                sC[st][tid-160]  = xb[DI + DSTATE + tid - 160];
            if (tid < 32)       sC[st][96+tid]   = xb[DI + DSTATE + 96 + tid];
        }
        if (tid < TCH) {
            int tok = b*LL + t0 + tid;
            sdt[tid] = g_dt[tok*NH + hh];
            sdA[tid] = g_dA[tok*NH + hh];
        }
        __syncthreads();
        #pragma unroll
        for (int st = 0; st < TCH; st++) {
            float dtt = sdt[st], dAt = sdA[st];
            float xp  = sx[st][pl];
            float dbx = dtt * xp;
            float y = 0.f;
            #pragma unroll
            for (int i = 0; i < 16; i++) {
                float hv = hreg[i]*dAt + dbx*sB[st][nb+i];
                hreg[i] = hv;
                y += hv * sC[st][nb+i];
            }
            y += __shfl_xor_sync(0xffffffffu, y, 1);
            y += __shfl_xor_sync(0xffffffffu, y, 2);
            y += __shfl_xor_sync(0xffffffffu, y, 4);
            if (ng == 0) {
                int tok = b*LL + t0 + st;
                g_y[(size_t)tok*DI + hh*HD + ps*32 + pl] = y + xp * Dh;
            }
        }
        __syncthreads();
    }
}

// ---------------- gated RMS norm -> y bf16 ----------------
__global__ void k_gatenorm(int l, const float* __restrict__ ssm_norm_w) {
    int t = blockIdx.x;
    __shared__ float sv[DI];
    float ss = 0.f;
    for (int d = threadIdx.x; d < DI; d += 256) {
        float z = g_zx[(size_t)t*DIP + d];
        float v = g_y[(size_t)t*DI + d] * siluf(z);
        sv[d] = v;
        ss += v*v;
    }
    ss = block_reduce_sum(ss);
    float rstd = rsqrtf(ss * (1.f/DI) + 1e-5f);
    for (int d = threadIdx.x; d < DI; d += 256)
        g_y_bf[(size_t)t*DI + d] = __float2bfloat16(sv[d] * rstd * ssm_norm_w[l*DI + d]);
}

// ---------------- u = ln_noaffine(hidden)*(1+sc_msa)+sh_msa ----------------
__global__ void k_post_mamba(int l) {
    int t = blockIdx.x;
    int b = t / LL;
    const float* aff = &g_aff[(l*BB + b)*6*DM];
    float vals[3];
    float s1 = 0.f;
    #pragma unroll
    for (int i = 0; i < 3; i++) {
        int d = threadIdx.x + i*256;
        float v = g_hidden[t*DM + d];
        vals[i] = v;
        s1 += v;
    }
    s1 = block_reduce_sum(s1);
    float mean = s1 * (1.f/DM);
    float s2 = 0.f;
    #pragma unroll
    for (int i = 0; i < 3; i++) { float c = vals[i] - mean; s2 += c*c; }
    s2 = block_reduce_sum(s2);
    float rstd = rsqrtf(s2 * (1.f/DM) + 1e-6f);
    #pragma unroll
    for (int i = 0; i < 3; i++) {
        int d = threadIdx.x + i*256;
        float x = (vals[i] - mean) * rstd;
        g_u_bf[t*DM + d] = __float2bfloat16(x * (1.f + aff[4*DM + d]) + aff[3*DM + d]);
    }
}

// ---------------- cross attention ----------------
__global__ __launch_bounds__(512) void k_attn(int l) {
    int qt = blockIdx.x, hh = blockIdx.y, b = blockIdx.z;
    int warp = threadIdx.x >> 5, lane = threadIdx.x & 31;
    const float* kp = g_kall + (size_t)l*BB*LCC*AINNER;
    const float* vp = g_vall + (size_t)l*BB*LCC*AINNER;
    __shared__ float Ks[64][65];
    __shared__ float Vs[64][64];
    __shared__ float Qs[16][64];
    __shared__ float Ps[16][64];
    for (int idx = threadIdx.x; idx < 64*64; idx += 512) {
        int m = idx >> 6, d = idx & 63;
        Ks[m][d] = kp[(size_t)(b*LCC + m)*AINNER + hh*ADD + d];
        Vs[m][d] = vp[(size_t)(b*LCC + m)*AINNER + hh*ADD + d];
    }
    for (int idx = threadIdx.x; idx < 16*64; idx += 512) {
        int q = idx >> 6, d = idx & 63;
        Qs[q][d] = g_q[(size_t)(b*LL + qt*16 + q)*AINNER + hh*ADD + d];
    }
    __syncthreads();
    int q = warp;
    float s0 = 0.f, s1 = 0.f;
    #pragma unroll 8
    for (int d = 0; d < 64; d++) {
        float qd = Qs[q][d];
        s0 += qd * Ks[lane][d];
        s1 += qd * Ks[lane+32][d];
    }
    s0 *= 0.125f; s1 *= 0.125f;
    float mx = fmaxf(s0, s1);
    #pragma unroll
    for (int o = 16; o > 0; o >>= 1) mx = fmaxf(mx, __shfl_xor_sync(0xffffffffu, mx, o));
    float e0 = expf(s0 - mx), e1 = expf(s1 - mx);
    float sum = e0 + e1;
    #pragma unroll
    for (int o = 16; o > 0; o >>= 1) sum += __shfl_xor_sync(0xffffffffu, sum, o);
    float inv = 1.f / sum;
    Ps[q][lane] = e0 * inv;
    Ps[q][lane+32] = e1 * inv;
    __syncwarp();
    float o0 = 0.f, o1 = 0.f;
    #pragma unroll 8
    for (int m = 0; m < 64; m++) {
        float pm = Ps[q][m];
        o0 += pm * Vs[m][lane];
        o1 += pm * Vs[m][lane+32];
    }
    size_t base = (size_t)(b*LL + qt*16 + q)*AINNER + hh*ADD;
    g_ao_bf[base + lane]      = __float2bfloat16(o0);
    g_ao_bf[base + lane + 32] = __float2bfloat16(o1);
}

// ---------------- final rmsnorm ----------------
__global__ void k_final(const float* __restrict__ norm_f_w, float* __restrict__ out) {
    int t = blockIdx.x;
    float vals[3];
    float ss = 0.f;
    #pragma unroll
    for (int i = 0; i < 3; i++) {
        int d = threadIdx.x + i*256;
        float v = g_hidden[t*DM + d] + g_resid[t*DM + d];
        vals[i] = v;
        ss += v*v;
    }
    ss = block_reduce_sum(ss);
    float rstd = rsqrtf(ss * (1.f/DM) + 1e-5f);
    #pragma unroll
    for (int i = 0; i < 3; i++) {
        int d = threadIdx.x + i*256;
        out[t*DM + d] = vals[i] * rstd * norm_f_w[d];
    }
}

// ---------------- host ----------------
#define GETSYM(p, T, s) do { void* tmp_; cudaGetSymbolAddress(&tmp_, s); p = (T*)tmp_; } while(0)

extern "C" void kernel_launch(void* const* d_in, const int* in_sizes, int n_in,
                              void* d_out, int out_size) {
    const float* hs        = (const float*)d_in[0];
    const float* ref       = (const float*)d_in[1];
    const float* norm_w    = (const float*)d_in[2];
    const float* ada_w     = (const float*)d_in[3];
    const float* ada_b     = (const float*)d_in[4];
    const float* in_w      = (const float*)d_in[5];
    const float* conv_w    = (const float*)d_in[6];
    const float* conv_b    = (const float*)d_in[7];
    const float* dt_bias   = (const float*)d_in[8];
    const float* A_log     = (const float*)d_in[9];
    const float* D_ssm     = (const float*)d_in[10];
    const float* ssm_nw    = (const float*)d_in[11];
    const float* out_w     = (const float*)d_in[12];
    const float* out_b     = (const float*)d_in[13];
    const float* q_w       = (const float*)d_in[14];
    const float* k_w       = (const float*)d_in[15];
    const float* v_w       = (const float*)d_in[16];
    const float* o_w       = (const float*)d_in[17];
    const float* o_b       = (const float*)d_in[18];
    const float* norm_f_w  = (const float*)d_in[19];
    float* out = (float*)d_out;

    static int smem_set = 0;
    if (!smem_set) {
        cudaFuncSetAttribute(gemm128, cudaFuncAttributeMaxDynamicSharedMemorySize, SM128_BYTES);
        smem_set = 1;
    }

    float *p_zx, *p_q, *p_y, *p_kall, *p_vall, *p_hidden, *p_aff;
    GETSYM(p_zx,    float, g_zx);
    GETSYM(p_q,     float, g_q);
    GETSYM(p_y,     float, g_y);
    GETSYM(p_kall,  float, g_kall);
    GETSYM(p_vall,  float, g_vall);
    GETSYM(p_hidden,float, g_hidden);
    GETSYM(p_aff,   float, g_aff);

    bf16 *u_bf,*y_bf,*ao_bf,*ref_bf,*wi_bf,*wo_bf,*wq_bf,*wk_bf,*wv_bf,*wp_bf;
    GETSYM(u_bf,  bf16, g_u_bf);
    GETSYM(y_bf,  bf16, g_y_bf);
    GETSYM(ao_bf, bf16, g_ao_bf);
    GETSYM(ref_bf,bf16, g_ref_bf);
    GETSYM(wi_bf, bf16, g_wi_bf);
    GETSYM(wo_bf, bf16, g_wo_bf);
    GETSYM(wq_bf, bf16, g_wq_bf);
    GETSYM(wk_bf, bf16, g_wk_bf);
    GETSYM(wv_bf, bf16, g_wv_bf);
    GETSYM(wp_bf, bf16, g_wp_bf);

    const int M = BB*LL;   // 1024
    #define CVT(src, dst, n) k_tobf16<<<((n)+255)/256, 256>>>(src, dst, n)

    CVT(ref, ref_bf, BB*LCC*DM);
    CVT(k_w, wk_bf, NLAYER*DM*AINNER);
    CVT(v_w, wv_bf, NLAYER*DM*AINNER);
    gemm128<<<dim3(AINNER/128, (BB*LCC)/128, NLAYER), 256, SM128_BYTES>>>(ref_bf, wk_bf,
        p_kall, BB*LCC, AINNER, DM, (long)DM*AINNER, (long)BB*LCC*AINNER);
    gemm128<<<dim3(AINNER/128, (BB*LCC)/128, NLAYER), 256, SM128_BYTES>>>(ref_bf, wv_bf,
        p_vall, BB*LCC, AINNER, DM, (long)DM*AINNER, (long)BB*LCC*AINNER);
    k_condsilu<<<(BB*DM + 255)/256, 256>>>(ref);
    k_ada<<<(NLAYER*BB*6*DM + 255)/256, 256>>>(ada_w, ada_b);
    CVT(in_w,  wi_bf, NLAYER*DM*DIP);
    CVT(out_w, wo_bf, NLAYER*DI*DM);
    CVT(q_w,   wq_bf, NLAYER*DM*AINNER);
    CVT(o_w,   wp_bf, NLAYER*AINNER*DM);

    for (int l = 0; l < NLAYER; l++) {
        k_prenorm_mod<<<M, 256>>>(l, hs, norm_w);
        gemm128<<<dim3((DIP+127)/128, M/128), 256, SM128_BYTES>>>(u_bf,
            wi_bf + (size_t)l*DM*DIP, p_zx, M, DIP, DM, 0, 0);
        k_conv<<<BB*7*8, 256>>>(l, conv_w, conv_b);
        k_dt<<<(BB*LL*NH + 255)/256, 256>>>(l, dt_bias, A_log);
        k_scan<<<dim3(BB*NH, 2), 256>>>(l, D_ssm);
        k_gatenorm<<<M, 256>>>(l, ssm_nw);
        gemm64<<<dim3(DM/64, M/64), 256>>>(y_bf, wo_bf + (size_t)l*DI*DM, out_b + l*DM,
            p_aff + (size_t)(l*BB)*6*DM + 2*DM, p_hidden, M, DM, DI, 0, 0);
        k_post_mamba<<<M, 256>>>(l);
        gemm64<<<dim3(AINNER/64, M/64), 256>>>(u_bf, wq_bf + (size_t)l*DM*AINNER, nullptr,
            nullptr, p_q, M, AINNER, DM, 0, 0);
        k_attn<<<dim3(LL/16, AHH, BB), 512>>>(l);
        gemm64<<<dim3(DM/64, M/64), 256>>>(ao_bf, wp_bf + (size_t)l*AINNER*DM, o_b + l*DM,
            p_aff + (size_t)(l*BB)*6*DM + 5*DM, p_hidden, M, DM, AINNER, 0, 0);
    }
    k_final<<<M, 256>>>(norm_f_w, out);
}

// round 16
// speedup vs baseline: 1.4558x; 1.3469x over previous
#include <cuda_runtime.h>
#include <cuda_bf16.h>
#include <math.h>
#include <stdint.h>

#define BB 2
#define LL 512
#define LCC 64
#define DM 768
#define DI 1536
#define NH 24
#define HD 64
#define DSTATE 128
#define CONVD 1792
#define DIP 3352
#define NLAYER 8
#define AHH 8
#define ADD 64
#define AINNER 512

typedef __nv_bfloat16 bf16;

// ---------------- scratch ----------------
__device__ float g_hidden[BB*LL*DM];
__device__ float g_resid [BB*LL*DM];
__device__ float g_zx    [BB*LL*DIP];
__device__ float g_xBC   [BB*LL*CONVD];
__device__ float g_dt    [BB*LL*NH];
__device__ float g_dA    [BB*LL*NH];
__device__ float g_y     [BB*LL*DI];
__device__ float g_q     [BB*LL*AINNER];
__device__ float g_kall  [NLAYER*BB*LCC*AINNER];
__device__ float g_vall  [NLAYER*BB*LCC*AINNER];
__device__ float g_aff   [NLAYER*BB*6*DM];
__device__ float g_csilu [BB*DM];

__device__ bf16 g_u_bf [BB*LL*DM];
__device__ bf16 g_y_bf [BB*LL*DI];
__device__ bf16 g_ao_bf[BB*LL*AINNER];
__device__ bf16 g_ref_bf[BB*LCC*DM];

__device__ bf16 g_wi_bf[NLAYER*DM*DIP];
__device__ bf16 g_wo_bf[NLAYER*DI*DM];
__device__ bf16 g_wq_bf[NLAYER*DM*AINNER];
__device__ bf16 g_wk_bf[NLAYER*DM*AINNER];
__device__ bf16 g_wv_bf[NLAYER*DM*AINNER];
__device__ bf16 g_wp_bf[NLAYER*AINNER*DM];

__device__ __forceinline__ float siluf(float x) { return x / (1.f + expf(-x)); }

__device__ __forceinline__ float block_reduce_sum(float v) {
    __shared__ float red_s[33];
    int lane = threadIdx.x & 31;
    int wid  = threadIdx.x >> 5;
    #pragma unroll
    for (int o = 16; o > 0; o >>= 1) v += __shfl_xor_sync(0xffffffffu, v, o);
    if (lane == 0) red_s[wid] = v;
    __syncthreads();
    int nw = (blockDim.x + 31) >> 5;
    if (wid == 0) {
        float x = (lane < nw) ? red_s[lane] : 0.f;
        #pragma unroll
        for (int o = 16; o > 0; o >>= 1) x += __shfl_xor_sync(0xffffffffu, x, o);
        if (lane == 0) red_s[32] = x;
    }
    __syncthreads();
    float r = red_s[32];
    __syncthreads();
    return r;
}

__global__ void k_tobf16(const float* __restrict__ src, bf16* __restrict__ dst, int n) {
    int i = blockIdx.x * 256 + threadIdx.x;
    if (i < n) dst[i] = __float2bfloat16(src[i]);
}

__global__ void k_condsilu(const float* __restrict__ ref) {
    int i = blockIdx.x * 256 + threadIdx.x;
    if (i >= BB*DM) return;
    int b = i / DM, d = i % DM;
    float s = 0.f;
    for (int m = 0; m < LCC; m++) s += ref[(b*LCC + m)*DM + d];
    s *= (1.f / LCC);
    g_csilu[i] = siluf(s);
}

__global__ void k_ada(const float* __restrict__ ada_w, const float* __restrict__ ada_b) {
    int i = blockIdx.x * 256 + threadIdx.x;
    if (i >= NLAYER*BB*6*DM) return;
    int j  = i % (6*DM);
    int lb = i / (6*DM);
    int b  = lb % BB;
    int l  = lb / BB;
    float s = ada_b[l*6*DM + j];
    const float* cs = &g_csilu[b*DM];
    const float* w  = ada_w + (size_t)l*DM*6*DM + j;
    for (int d = 0; d < DM; d++) s += cs[d] * w[(size_t)d*6*DM];
    g_aff[i] = s;
}

// ================= bf16 tensor-core GEMM =================
__device__ __forceinline__ void ldsm4(uint32_t* r, uint32_t addr) {
    asm volatile("ldmatrix.sync.aligned.m8n8.x4.shared.b16 {%0,%1,%2,%3}, [%4];"
        : "=r"(r[0]), "=r"(r[1]), "=r"(r[2]), "=r"(r[3]) : "r"(addr));
}
__device__ __forceinline__ void ldsm4t(uint32_t* r, uint32_t addr) {
    asm volatile("ldmatrix.sync.aligned.m8n8.x4.trans.shared.b16 {%0,%1,%2,%3}, [%4];"
        : "=r"(r[0]), "=r"(r[1]), "=r"(r[2]), "=r"(r[3]) : "r"(addr));
}
__device__ __forceinline__ void mma_bf16(float* d, const uint32_t* a, uint32_t b0, uint32_t b1) {
    asm volatile("mma.sync.aligned.m16n8k16.row.col.f32.bf16.bf16.f32 "
        "{%0,%1,%2,%3}, {%4,%5,%6,%7}, {%8,%9}, {%0,%1,%2,%3};"
        : "+f"(d[0]), "+f"(d[1]), "+f"(d[2]), "+f"(d[3])
        : "r"(a[0]), "r"(a[1]), "r"(a[2]), "r"(a[3]), "r"(b0), "r"(b1));
}
__device__ __forceinline__ void cp16(void* smem, const void* gmem) {
    uint32_t s = (uint32_t)__cvta_generic_to_shared(smem);
    asm volatile("cp.async.cg.shared.global [%0], [%1], 16;" :: "r"(s), "l"(gmem));
}

#define AP 40    // A smem pitch (bf16)
#define BP 136   // B smem pitch (bf16)

// ---------------- 128x128 tile, 3-stage pipeline, 2 CTAs/SM, z-batched ----------------
#define OFF_B128 (128*AP)
#define STG128   (128*AP + 32*BP)
#define SM128_BYTES (3*STG128*2)   // 56832

__global__ __launch_bounds__(256, 2) void gemm128(const bf16* __restrict__ A,
                                                  const bf16* __restrict__ W,
                                                  float* __restrict__ C,
                                                  int M, int N, int K,
                                                  long wz, long cz) {
    extern __shared__ bf16 sm[];
    W += (size_t)blockIdx.z * wz;
    C += (size_t)blockIdx.z * cz;

    int tid = threadIdx.x;
    int n0 = blockIdx.x * 128, m0 = blockIdx.y * 128;
    int warp = tid >> 5, lane = tid & 31;
    int wm = warp >> 2, wn = warp & 3;

    int a_row = tid >> 1, a_off = (tid & 1) * 16;
    int b_row0 = tid >> 4, b_off = (tid & 15) * 8;

    float acc[4][4][4];
    #pragma unroll
    for (int i = 0; i < 4; i++)
        #pragma unroll
        for (int j = 0; j < 4; j++)
            #pragma unroll
            for (int v = 0; v < 4; v++) acc[i][j][v] = 0.f;

    int nt = K >> 5;

    auto load_tile = [&](int it, int st) {
        bf16* base = sm + st*STG128;
        const bf16* src = A + (size_t)(m0 + a_row)*K + it*32 + a_off;
        cp16(&base[a_row*AP + a_off],     src);
        cp16(&base[a_row*AP + a_off + 8], src + 8);
        #pragma unroll
        for (int s = 0; s < 2; s++) {
            int row = b_row0 + s*16;
            int col = n0 + b_off;
            if (col < N) {
                cp16(&base[OFF_B128 + row*BP + b_off], W + (size_t)(it*32 + row)*N + col);
            } else {
                *reinterpret_cast<uint4*>(&base[OFF_B128 + row*BP + b_off]) = make_uint4(0,0,0,0);
            }
        }
        asm volatile("cp.async.commit_group;");
    };

    load_tile(0, 0);
    load_tile(1, 1);

    int st = 0, st_next = 2;
    for (int it = 0; it < nt; it++) {
        if (it + 2 < nt) {
            load_tile(it + 2, st_next);
            asm volatile("cp.async.wait_group 2;");
        } else {
            asm volatile("cp.async.wait_group 0;");
        }
        __syncthreads();

        bf16* base = sm + st*STG128;
        #pragma unroll
        for (int kt = 0; kt < 2; kt++) {
            int kk = kt * 16;
            uint32_t af[4][4];
            #pragma unroll
            for (int mt = 0; mt < 4; mt++) {
                int r = wm*64 + mt*16 + (lane & 15);
                int c = kk + (lane >> 4)*8;
                ldsm4(af[mt], (uint32_t)__cvta_generic_to_shared(&base[r*AP + c]));
            }
            uint32_t bfr[2][4];
            #pragma unroll
            for (int np = 0; np < 2; np++) {
                int kr = kk + (lane & 15);
                int c  = wn*32 + np*16 + (lane >> 4)*8;
                ldsm4t(bfr[np], (uint32_t)__cvta_generic_to_shared(&base[OFF_B128 + kr*BP + c]));
            }
            #pragma unroll
            for (int mt = 0; mt < 4; mt++)
                #pragma unroll
                for (int nt2 = 0; nt2 < 4; nt2++) {
                    int np = nt2 >> 1, s = (nt2 & 1)*2;
                    mma_bf16(acc[mt][nt2], af[mt], bfr[np][s], bfr[np][s+1]);
                }
        }
        __syncthreads();
        st = (st == 2) ? 0 : st + 1;
        st_next = (st_next == 2) ? 0 : st_next + 1;
    }

    int gr = lane >> 2, gc = (lane & 3)*2;
    #pragma unroll
    for (int mt = 0; mt < 4; mt++) {
        #pragma unroll
        for (int nt2 = 0; nt2 < 4; nt2++) {
            int row0 = m0 + wm*64 + mt*16 + gr;
            int col0 = n0 + wn*32 + nt2*8 + gc;
            if (col0 < N) {
                C[(size_t)row0*N + col0]     = acc[mt][nt2][0];
                C[(size_t)(row0+8)*N + col0] = acc[mt][nt2][2];
            }
            if (col0 + 1 < N) {
                C[(size_t)row0*N + col0+1]     = acc[mt][nt2][1];
                C[(size_t)(row0+8)*N + col0+1] = acc[mt][nt2][3];
            }
        }
    }
}

// ---------------- 64x64 tile (small GEMMs), 4-stage pipeline ----------------
#define BP64 72
#define OFF_B64 (64*AP)
#define STG64   (64*AP + 32*BP64)

__global__ __launch_bounds__(256) void gemm64(const bf16* __restrict__ A,
                                              const bf16* __restrict__ W,
                                              const float* __restrict__ bias,
                                              const float* __restrict__ gate,
                                              float* __restrict__ C,
                                              int M, int N, int K,
                                              long wz, long cz) {
    __shared__ bf16 sm[4*STG64];

    W += (size_t)blockIdx.z * wz;
    C += (size_t)blockIdx.z * cz;

    int tid = threadIdx.x;
    int n0 = blockIdx.x * 64, m0 = blockIdx.y * 64;
    int warp = tid >> 5, lane = tid & 31;
    int wm = warp >> 2, wn = warp & 3;

    int a_row = tid >> 2, a_off = (tid & 3) * 8;
    int b_row = tid >> 3, b_off = (tid & 7) * 8;

    float acc[2][2][4];
    #pragma unroll
    for (int i = 0; i < 2; i++)
        #pragma unroll
        for (int j = 0; j < 2; j++)
            #pragma unroll
            for (int v = 0; v < 4; v++) acc[i][j][v] = 0.f;

    int nt = K >> 5;

    auto load_tile = [&](int it, int st) {
        bf16* base = sm + st*STG64;
        cp16(&base[a_row*AP + a_off], A + (size_t)(m0 + a_row)*K + it*32 + a_off);
        int col = n0 + b_off;
        if (col < N) {
            cp16(&base[OFF_B64 + b_row*BP64 + b_off], W + (size_t)(it*32 + b_row)*N + col);
        } else {
            *reinterpret_cast<uint4*>(&base[OFF_B64 + b_row*BP64 + b_off]) = make_uint4(0,0,0,0);
        }
        asm volatile("cp.async.commit_group;");
    };

    load_tile(0, 0);
    load_tile(1, 1);
    load_tile(2, 2);

    for (int it = 0; it < nt; it++) {
        if (it + 3 < nt) {
            load_tile(it + 3, (it + 3) & 3);
            asm volatile("cp.async.wait_group 3;");
        } else {
            asm volatile("cp.async.wait_group 0;");
        }
        __syncthreads();

        bf16* base = sm + (it & 3)*STG64;
        #pragma unroll
        for (int kt = 0; kt < 2; kt++) {
            int kk = kt * 16;
            uint32_t af[2][4];
            #pragma unroll
            for (int mt = 0; mt < 2; mt++) {
                int r = wm*32 + mt*16 + (lane & 15);
                int c = kk + (lane >> 4)*8;
                ldsm4(af[mt], (uint32_t)__cvta_generic_to_shared(&base[r*AP + c]));
            }
            uint32_t bfr[4];
            {
                int kr = kk + (lane & 15);
                int c  = wn*16 + (lane >> 4)*8;
                ldsm4t(bfr, (uint32_t)__cvta_generic_to_shared(&base[OFF_B64 + kr*BP64 + c]));
            }
            #pragma unroll
            for (int mt = 0; mt < 2; mt++)
                #pragma unroll
                for (int nt2 = 0; nt2 < 2; nt2++) {
                    int s = nt2*2;
                    mma_bf16(acc[mt][nt2], af[mt], bfr[s], bfr[s+1]);
                }
        }
        __syncthreads();
    }

    int gr = lane >> 2, gc = (lane & 3)*2;
    #pragma unroll
    for (int mt = 0; mt < 2; mt++) {
        int row0 = m0 + wm*32 + mt*16 + gr;
        int bidx = row0 / LL;
        #pragma unroll
        for (int nt2 = 0; nt2 < 2; nt2++) {
            int col0 = n0 + wn*16 + nt2*8 + gc;
            float b0 = bias ? bias[col0] : 0.f;
            float b1 = bias ? bias[col0+1] : 0.f;
            float v00 = acc[mt][nt2][0] + b0, v01 = acc[mt][nt2][1] + b1;
            float v10 = acc[mt][nt2][2] + b0, v11 = acc[mt][nt2][3] + b1;
            if (col0 < N) {
                if (gate) {
                    float gv0 = gate[bidx*6*DM + col0];
                    float gv1 = gate[bidx*6*DM + col0 + 1];
                    C[(size_t)row0*N + col0]       += gv0 * v00;
                    C[(size_t)row0*N + col0+1]     += gv1 * v01;
                    C[(size_t)(row0+8)*N + col0]   += gv0 * v10;
                    C[(size_t)(row0+8)*N + col0+1] += gv1 * v11;
                } else {
                    C[(size_t)row0*N + col0]       = v00;
                    C[(size_t)row0*N + col0+1]     = v01;
                    C[(size_t)(row0+8)*N + col0]   = v10;
                    C[(size_t)(row0+8)*N + col0+1] = v11;
                }
            }
        }
    }
}

// ---------------- pre-norm + AdaLN modulation (l==0 reads hs) ----------------
__global__ void k_prenorm_mod(int l, const float* __restrict__ hs,
                              const float* __restrict__ norm_w) {
    int t = blockIdx.x;
    int b = t / LL;
    const float* aff = &g_aff[(l*BB + b)*6*DM];
    float vals[3];
    float ss = 0.f;
    #pragma unroll
    for (int i = 0; i < 3; i++) {
        int d = threadIdx.x + i*256;
        float v = (l == 0) ? hs[t*DM + d]
                           : (g_resid[t*DM + d] + g_hidden[t*DM + d]);
        g_resid[t*DM + d] = v;
        vals[i] = v;
        ss += v*v;
    }
    ss = block_reduce_sum(ss);
    float rstd = rsqrtf(ss * (1.f/DM) + 1e-5f);
    #pragma unroll
    for (int i = 0; i < 3; i++) {
        int d = threadIdx.x + i*256;
        float x = vals[i] * rstd * norm_w[l*DM + d];
        g_hidden[t*DM + d] = x;
        g_u_bf[t*DM + d] = __float2bfloat16(x * (1.f + aff[DM + d]) + aff[d]);
    }
}

// ---------------- conv + dt (R13 version: high thread parallelism) ----------------
__global__ void k_conv_dt(int l, const float* __restrict__ conv_w,
                          const float* __restrict__ conv_b,
                          const float* __restrict__ dt_bias,
                          const float* __restrict__ A_log) {
    int t  = blockIdx.x;
    int b  = t / LL, tt = t % LL;
    for (int c = threadIdx.x; c < CONVD; c += 256) {
        const float* wc = conv_w + (l*CONVD + c)*4;
        float acc = conv_b[l*CONVD + c];
        #pragma unroll
        for (int j = 0; j < 4; j++) {
            int ts = tt - 3 + j;
            if (ts >= 0) acc += wc[j] * g_zx[(size_t)(b*LL + ts)*DIP + DI + c];
        }
        g_xBC[(size_t)t*CONVD + c] = siluf(acc);
    }
    if (threadIdx.x < NH) {
        int hh = threadIdx.x;
        float x = g_zx[(size_t)t*DIP + DI + CONVD + hh] + dt_bias[l*NH + hh];
        float dt = (x > 20.f) ? x : log1pf(expf(x));
        g_dt[t*NH + hh] = dt;
        g_dA[t*NH + hh] = expf(-expf(A_log[l*NH + hh]) * dt);
    }
}

// ---------------- SSM scan: register-prefetch double-buffered ----------------
#define TCH 8
__global__ __launch_bounds__(256) void k_scan(int l, const float* __restrict__ D_ssm) {
    int bh = blockIdx.x;
    int b = bh / NH, hh = bh % NH;
    int ps = blockIdx.y;
    int tid = threadIdx.x;
    int pl = tid >> 3;
    int ng = tid & 7;
    int nb = ng * 16;
    float hreg[16];
    #pragma unroll
    for (int i = 0; i < 16; i++) hreg[i] = 0.f;

    __shared__ float sx[TCH][32];
    __shared__ float sB[TCH][DSTATE];
    __shared__ float sC[TCH][DSTATE];
    __shared__ float sdt[TCH], sdA[TCH];
    float Dh = D_ssm[l*NH + hh];

    // per-thread global offset for its role (uniform across chunks)
    int goff;
    if (tid < 32)       goff = hh*HD + ps*32 + tid;
    else if (tid < 160) goff = DI + tid - 32;
    else                goff = DI + DSTATE + tid - 160;
    int goff2 = DI + DSTATE + 96 + tid;   // valid for tid<32

    float rv[TCH], rv2[TCH];
    float rdt = 0.f, rdA = 0.f;

    auto issue_loads = [&](int t0) {
        #pragma unroll
        for (int st = 0; st < TCH; st++) {
            const float* xb = g_xBC + (size_t)(b*LL + t0 + st)*CONVD;
            rv[st] = xb[goff];
            if (tid < 32) rv2[st] = xb[goff2];
        }
        if (tid < TCH) {
            int tok = b*LL + t0 + tid;
            rdt = g_dt[tok*NH + hh];
            rdA = g_dA[tok*NH + hh];
        }
    };

    issue_loads(0);

    for (int t0 = 0; t0 < LL; t0 += TCH) {
        // stage regs -> smem
        #pragma unroll
        for (int st = 0; st < TCH; st++) {
            if (tid < 32)       { sx[st][tid] = rv[st]; sC[st][96+tid] = rv2[st]; }
            else if (tid < 160) sB[st][tid-32]  = rv[st];
            else                sC[st][tid-160] = rv[st];
        }
        if (tid < TCH) { sdt[tid] = rdt; sdA[tid] = rdA; }
        __syncthreads();
        // prefetch next chunk into regs while computing this one
        if (t0 + TCH < LL) issue_loads(t0 + TCH);
        #pragma unroll
        for (int st = 0; st < TCH; st++) {
            float dtt = sdt[st], dAt = sdA[st];
            float xp  = sx[st][pl];
            float dbx = dtt * xp;
            float y = 0.f;
            #pragma unroll
            for (int i = 0; i < 16; i++) {
                float hv = hreg[i]*dAt + dbx*sB[st][nb+i];
                hreg[i] = hv;
                y += hv * sC[st][nb+i];
            }
            y += __shfl_xor_sync(0xffffffffu, y, 1);
            y += __shfl_xor_sync(0xffffffffu, y, 2);
            y += __shfl_xor_sync(0xffffffffu, y, 4);
            if (ng == 0) {
                int tok = b*LL + t0 + st;
                g_y[(size_t)tok*DI + hh*HD + ps*32 + pl] = y + xp * Dh;
            }
        }
        __syncthreads();
    }
}

// ---------------- gated RMS norm -> y bf16 ----------------
__global__ void k_gatenorm(int l, const float* __restrict__ ssm_norm_w) {
    int t = blockIdx.x;
    __shared__ float sv[DI];
    float ss = 0.f;
    for (int d = threadIdx.x; d < DI; d += 256) {
        float z = g_zx[(size_t)t*DIP + d];
        float v = g_y[(size_t)t*DI + d] * siluf(z);
        sv[d] = v;
        ss += v*v;
    }
    ss = block_reduce_sum(ss);
    float rstd = rsqrtf(ss * (1.f/DI) + 1e-5f);
    for (int d = threadIdx.x; d < DI; d += 256)
        g_y_bf[(size_t)t*DI + d] = __float2bfloat16(sv[d] * rstd * ssm_norm_w[l*DI + d]);
}

// ---------------- u = ln_noaffine(hidden)*(1+sc_msa)+sh_msa ----------------
__global__ void k_post_mamba(int l) {
    int t = blockIdx.x;
    int b = t / LL;
    const float* aff = &g_aff[(l*BB + b)*6*DM];
    float vals[3];
    float s1 = 0.f;
    #pragma unroll
    for (int i = 0; i < 3; i++) {
        int d = threadIdx.x + i*256;
        float v = g_hidden[t*DM + d];
        vals[i] = v;
        s1 += v;
    }
    s1 = block_reduce_sum(s1);
    float mean = s1 * (1.f/DM);
    float s2 = 0.f;
    #pragma unroll
    for (int i = 0; i < 3; i++) { float c = vals[i] - mean; s2 += c*c; }
    s2 = block_reduce_sum(s2);
    float rstd = rsqrtf(s2 * (1.f/DM) + 1e-6f);
    #pragma unroll
    for (int i = 0; i < 3; i++) {
        int d = threadIdx.x + i*256;
        float x = (vals[i] - mean) * rstd;
        g_u_bf[t*DM + d] = __float2bfloat16(x * (1.f + aff[4*DM + d]) + aff[3*DM + d]);
    }
}

// ---------------- cross attention ----------------
__global__ __launch_bounds__(512) void k_attn(int l) {
    int qt = blockIdx.x, hh = blockIdx.y, b = blockIdx.z;
    int warp = threadIdx.x >> 5, lane = threadIdx.x & 31;
    const float* kp = g_kall + (size_t)l*BB*LCC*AINNER;
    const float* vp = g_vall + (size_t)l*BB*LCC*AINNER;
    __shared__ float Ks[64][65];
    __shared__ float Vs[64][64];
    __shared__ float Qs[16][64];
    __shared__ float Ps[16][64];
    for (int idx = threadIdx.x; idx < 64*64; idx += 512) {
        int m = idx >> 6, d = idx & 63;
        Ks[m][d] = kp[(size_t)(b*LCC + m)*AINNER + hh*ADD + d];
        Vs[m][d] = vp[(size_t)(b*LCC + m)*AINNER + hh*ADD + d];
    }
    for (int idx = threadIdx.x; idx < 16*64; idx += 512) {
        int q = idx >> 6, d = idx & 63;
        Qs[q][d] = g_q[(size_t)(b*LL + qt*16 + q)*AINNER + hh*ADD + d];
    }
    __syncthreads();
    int q = warp;
    float s0 = 0.f, s1 = 0.f;
    #pragma unroll 8
    for (int d = 0; d < 64; d++) {
        float qd = Qs[q][d];
        s0 += qd * Ks[lane][d];
        s1 += qd * Ks[lane+32][d];
    }
    s0 *= 0.125f; s1 *= 0.125f;
    float mx = fmaxf(s0, s1);
    #pragma unroll
    for (int o = 16; o > 0; o >>= 1) mx = fmaxf(mx, __shfl_xor_sync(0xffffffffu, mx, o));
    float e0 = expf(s0 - mx), e1 = expf(s1 - mx);
    float sum = e0 + e1;
    #pragma unroll
    for (int o = 16; o > 0; o >>= 1) sum += __shfl_xor_sync(0xffffffffu, sum, o);
    float inv = 1.f / sum;
    Ps[q][lane] = e0 * inv;
    Ps[q][lane+32] = e1 * inv;
    __syncwarp();
    float o0 = 0.f, o1 = 0.f;
    #pragma unroll 8
    for (int m = 0; m < 64; m++) {
        float pm = Ps[q][m];
        o0 += pm * Vs[m][lane];
        o1 += pm * Vs[m][lane+32];
    }
    size_t base = (size_t)(b*LL + qt*16 + q)*AINNER + hh*ADD;
    g_ao_bf[base + lane]      = __float2bfloat16(o0);
    g_ao_bf[base + lane + 32] = __float2bfloat16(o1);
}

// ---------------- final rmsnorm ----------------
__global__ void k_final(const float* __restrict__ norm_f_w, float* __restrict__ out) {
    int t = blockIdx.x;
    float vals[3];
    float ss = 0.f;
    #pragma unroll
    for (int i = 0; i < 3; i++) {
        int d = threadIdx.x + i*256;
        float v = g_hidden[t*DM + d] + g_resid[t*DM + d];
        vals[i] = v;
        ss += v*v;
    }
    ss = block_reduce_sum(ss);
    float rstd = rsqrtf(ss * (1.f/DM) + 1e-5f);
    #pragma unroll
    for (int i = 0; i < 3; i++) {
        int d = threadIdx.x + i*256;
        out[t*DM + d] = vals[i] * rstd * norm_f_w[d];
    }
}

// ---------------- host ----------------
#define GETSYM(p, T, s) do { void* tmp_; cudaGetSymbolAddress(&tmp_, s); p = (T*)tmp_; } while(0)

extern "C" void kernel_launch(void* const* d_in, const int* in_sizes, int n_in,
                              void* d_out, int out_size) {
    const float* hs        = (const float*)d_in[0];
    const float* ref       = (const float*)d_in[1];
    const float* norm_w    = (const float*)d_in[2];
    const float* ada_w     = (const float*)d_in[3];
    const float* ada_b     = (const float*)d_in[4];
    const float* in_w      = (const float*)d_in[5];
    const float* conv_w    = (const float*)d_in[6];
    const float* conv_b    = (const float*)d_in[7];
    const float* dt_bias   = (const float*)d_in[8];
    const float* A_log     = (const float*)d_in[9];
    const float* D_ssm     = (const float*)d_in[10];
    const float* ssm_nw    = (const float*)d_in[11];
    const float* out_w     = (const float*)d_in[12];
    const float* out_b     = (const float*)d_in[13];
    const float* q_w       = (const float*)d_in[14];
    const float* k_w       = (const float*)d_in[15];
    const float* v_w       = (const float*)d_in[16];
    const float* o_w       = (const float*)d_in[17];
    const float* o_b       = (const float*)d_in[18];
    const float* norm_f_w  = (const float*)d_in[19];
    float* out = (float*)d_out;

    static int smem_set = 0;
    if (!smem_set) {
        cudaFuncSetAttribute(gemm128, cudaFuncAttributeMaxDynamicSharedMemorySize, SM128_BYTES);
        smem_set = 1;
    }

    float *p_zx, *p_q, *p_y, *p_kall, *p_vall, *p_hidden, *p_aff;
    GETSYM(p_zx,    float, g_zx);
    GETSYM(p_q,     float, g_q);
    GETSYM(p_y,     float, g_y);
    GETSYM(p_kall,  float, g_kall);
    GETSYM(p_vall,  float, g_vall);
    GETSYM(p_hidden,float, g_hidden);
    GETSYM(p_aff,   float, g_aff);

    bf16 *u_bf,*y_bf,*ao_bf,*ref_bf,*wi_bf,*wo_bf,*wq_bf,*wk_bf,*wv_bf,*wp_bf;
    GETSYM(u_bf,  bf16, g_u_bf);
    GETSYM(y_bf,  bf16, g_y_bf);
    GETSYM(ao_bf, bf16, g_ao_bf);
    GETSYM(ref_bf,bf16, g_ref_bf);
    GETSYM(wi_bf, bf16, g_wi_bf);
    GETSYM(wo_bf, bf16, g_wo_bf);
    GETSYM(wq_bf, bf16, g_wq_bf);
    GETSYM(wk_bf, bf16, g_wk_bf);
    GETSYM(wv_bf, bf16, g_wv_bf);
    GETSYM(wp_bf, bf16, g_wp_bf);

    const int M = BB*LL;   // 1024
    #define CVT(src, dst, n) k_tobf16<<<((n)+255)/256, 256>>>(src, dst, n)

    CVT(ref, ref_bf, BB*LCC*DM);
    CVT(k_w, wk_bf, NLAYER*DM*AINNER);
    CVT(v_w, wv_bf, NLAYER*DM*AINNER);
    // kv projections via gemm64 (measured faster: 12us vs 20us per launch)
    gemm64<<<dim3(AINNER/64, (BB*LCC)/64, NLAYER), 256>>>(ref_bf, wk_bf, nullptr, nullptr,
        p_kall, BB*LCC, AINNER, DM, (long)DM*AINNER, (long)BB*LCC*AINNER);
    gemm64<<<dim3(AINNER/64, (BB*LCC)/64, NLAYER), 256>>>(ref_bf, wv_bf, nullptr, nullptr,
        p_vall, BB*LCC, AINNER, DM, (long)DM*AINNER, (long)BB*LCC*AINNER);
    k_condsilu<<<(BB*DM + 255)/256, 256>>>(ref);
    k_ada<<<(NLAYER*BB*6*DM + 255)/256, 256>>>(ada_w, ada_b);
    CVT(in_w,  wi_bf, NLAYER*DM*DIP);
    CVT(out_w, wo_bf, NLAYER*DI*DM);
    CVT(q_w,   wq_bf, NLAYER*DM*AINNER);
    CVT(o_w,   wp_bf, NLAYER*AINNER*DM);

    for (int l = 0; l < NLAYER; l++) {
        k_prenorm_mod<<<M, 256>>>(l, hs, norm_w);
        gemm128<<<dim3((DIP+127)/128, M/128), 256, SM128_BYTES>>>(u_bf,
            wi_bf + (size_t)l*DM*DIP, p_zx, M, DIP, DM, 0, 0);
        k_conv_dt<<<M, 256>>>(l, conv_w, conv_b, dt_bias, A_log);
        k_scan<<<dim3(BB*NH, 2), 256>>>(l, D_ssm);
        k_gatenorm<<<M, 256>>>(l, ssm_nw);
        gemm64<<<dim3(DM/64, M/64), 256>>>(y_bf, wo_bf + (size_t)l*DI*DM, out_b + l*DM,
            p_aff + (size_t)(l*BB)*6*DM + 2*DM, p_hidden, M, DM, DI, 0, 0);
        k_post_mamba<<<M, 256>>>(l);
        gemm64<<<dim3(AINNER/64, M/64), 256>>>(u_bf, wq_bf + (size_t)l*DM*AINNER, nullptr,
            nullptr, p_q, M, AINNER, DM, 0, 0);
        k_attn<<<dim3(LL/16, AHH, BB), 512>>>(l);
        gemm64<<<dim3(DM/64, M/64), 256>>>(ao_bf, wp_bf + (size_t)l*AINNER*DM, o_b + l*DM,
            p_aff + (size_t)(l*BB)*6*DM + 5*DM, p_hidden, M, DM, AINNER, 0, 0);
    }
    k_final<<<M, 256>>>(norm_f_w, out);
}

// round 17
// speedup vs baseline: 1.4742x; 1.0126x over previous
#include <cuda_runtime.h>
#include <cuda_bf16.h>
#include <math.h>
#include <stdint.h>

#define BB 2
#define LL 512
#define LCC 64
#define DM 768
#define DI 1536
#define NH 24
#define HD 64
#define DSTATE 128
#define CONVD 1792
#define DIP 3352
#define NLAYER 8
#define AHH 8
#define ADD 64
#define AINNER 512

typedef __nv_bfloat16 bf16;

// ---------------- scratch ----------------
__device__ float g_hidden[BB*LL*DM];
__device__ float g_resid [BB*LL*DM];
__device__ float g_zx    [BB*LL*DIP];
__device__ float g_xBC   [BB*LL*CONVD];
__device__ float g_dt    [BB*LL*NH];
__device__ float g_dA    [BB*LL*NH];
__device__ float g_y     [BB*LL*DI];
__device__ float g_q     [BB*LL*AINNER];
__device__ float g_kall  [NLAYER*BB*LCC*AINNER];
__device__ float g_vall  [NLAYER*BB*LCC*AINNER];
__device__ float g_aff   [NLAYER*BB*6*DM];
__device__ float g_csilu [BB*DM];

__device__ bf16 g_u_bf [BB*LL*DM];
__device__ bf16 g_y_bf [BB*LL*DI];
__device__ bf16 g_ao_bf[BB*LL*AINNER];
__device__ bf16 g_ref_bf[BB*LCC*DM];

__device__ bf16 g_wi_bf[NLAYER*DM*DIP];
__device__ bf16 g_wo_bf[NLAYER*DI*DM];
__device__ bf16 g_wq_bf[NLAYER*DM*AINNER];
__device__ bf16 g_wk_bf[NLAYER*DM*AINNER];
__device__ bf16 g_wv_bf[NLAYER*DM*AINNER];
__device__ bf16 g_wp_bf[NLAYER*AINNER*DM];

__device__ __forceinline__ float siluf(float x) { return x / (1.f + expf(-x)); }

__device__ __forceinline__ float block_reduce_sum(float v) {
    __shared__ float red_s[33];
    int lane = threadIdx.x & 31;
    int wid  = threadIdx.x >> 5;
    #pragma unroll
    for (int o = 16; o > 0; o >>= 1) v += __shfl_xor_sync(0xffffffffu, v, o);
    if (lane == 0) red_s[wid] = v;
    __syncthreads();
    int nw = (blockDim.x + 31) >> 5;
    if (wid == 0) {
        float x = (lane < nw) ? red_s[lane] : 0.f;
        #pragma unroll
        for (int o = 16; o > 0; o >>= 1) x += __shfl_xor_sync(0xffffffffu, x, o);
        if (lane == 0) red_s[32] = x;
    }
    __syncthreads();
    float r = red_s[32];
    __syncthreads();
    return r;
}

// ---------------- vectorized convert: 4 floats/thread ----------------
__global__ void k_tobf16v(const float* __restrict__ src, bf16* __restrict__ dst, int n4) {
    int i = blockIdx.x * 256 + threadIdx.x;   // index in float4 units
    if (i < n4) {
        float4 v = reinterpret_cast<const float4*>(src)[i];
        __nv_bfloat162 lo = __floats2bfloat162_rn(v.x, v.y);
        __nv_bfloat162 hi = __floats2bfloat162_rn(v.z, v.w);
        reinterpret_cast<__nv_bfloat162*>(dst)[i*2]   = lo;
        reinterpret_cast<__nv_bfloat162*>(dst)[i*2+1] = hi;
    }
}

__global__ void k_condsilu(const float* __restrict__ ref) {
    int i = blockIdx.x * 256 + threadIdx.x;
    if (i >= BB*DM) return;
    int b = i / DM, d = i % DM;
    float s = 0.f;
    for (int m = 0; m < LCC; m++) s += ref[(b*LCC + m)*DM + d];
    s *= (1.f / LCC);
    g_csilu[i] = siluf(s);
}

__global__ void k_ada(const float* __restrict__ ada_w, const float* __restrict__ ada_b) {
    int i = blockIdx.x * 256 + threadIdx.x;
    if (i >= NLAYER*BB*6*DM) return;
    int j  = i % (6*DM);
    int lb = i / (6*DM);
    int b  = lb % BB;
    int l  = lb / BB;
    float s = ada_b[l*6*DM + j];
    const float* cs = &g_csilu[b*DM];
    const float* w  = ada_w + (size_t)l*DM*6*DM + j;
    for (int d = 0; d < DM; d++) s += cs[d] * w[(size_t)d*6*DM];
    g_aff[i] = s;
}

// ================= bf16 tensor-core GEMM =================
__device__ __forceinline__ void ldsm4(uint32_t* r, uint32_t addr) {
    asm volatile("ldmatrix.sync.aligned.m8n8.x4.shared.b16 {%0,%1,%2,%3}, [%4];"
        : "=r"(r[0]), "=r"(r[1]), "=r"(r[2]), "=r"(r[3]) : "r"(addr));
}
__device__ __forceinline__ void ldsm4t(uint32_t* r, uint32_t addr) {
    asm volatile("ldmatrix.sync.aligned.m8n8.x4.trans.shared.b16 {%0,%1,%2,%3}, [%4];"
        : "=r"(r[0]), "=r"(r[1]), "=r"(r[2]), "=r"(r[3]) : "r"(addr));
}
__device__ __forceinline__ void mma_bf16(float* d, const uint32_t* a, uint32_t b0, uint32_t b1) {
    asm volatile("mma.sync.aligned.m16n8k16.row.col.f32.bf16.bf16.f32 "
        "{%0,%1,%2,%3}, {%4,%5,%6,%7}, {%8,%9}, {%0,%1,%2,%3};"
        : "+f"(d[0]), "+f"(d[1]), "+f"(d[2]), "+f"(d[3])
        : "r"(a[0]), "r"(a[1]), "r"(a[2]), "r"(a[3]), "r"(b0), "r"(b1));
}
__device__ __forceinline__ void cp16(void* smem, const void* gmem) {
    uint32_t s = (uint32_t)__cvta_generic_to_shared(smem);
    asm volatile("cp.async.cg.shared.global [%0], [%1], 16;" :: "r"(s), "l"(gmem));
}

#define AP 40    // A smem pitch (bf16)
#define BP 136   // B smem pitch (bf16)

// ---------------- 128x128 tile, 3-stage pipeline, 2 CTAs/SM, z-batched ----------------
#define OFF_B128 (128*AP)
#define STG128   (128*AP + 32*BP)
#define SM128_BYTES (3*STG128*2)   // 56832

__global__ __launch_bounds__(256, 2) void gemm128(const bf16* __restrict__ A,
                                                  const bf16* __restrict__ W,
                                                  float* __restrict__ C,
                                                  int M, int N, int K,
                                                  long wz, long cz) {
    extern __shared__ bf16 sm[];
    W += (size_t)blockIdx.z * wz;
    C += (size_t)blockIdx.z * cz;

    int tid = threadIdx.x;
    int n0 = blockIdx.x * 128, m0 = blockIdx.y * 128;
    int warp = tid >> 5, lane = tid & 31;
    int wm = warp >> 2, wn = warp & 3;

    int a_row = tid >> 1, a_off = (tid & 1) * 16;
    int b_row0 = tid >> 4, b_off = (tid & 15) * 8;

    float acc[4][4][4];
    #pragma unroll
    for (int i = 0; i < 4; i++)
        #pragma unroll
        for (int j = 0; j < 4; j++)
            #pragma unroll
            for (int v = 0; v < 4; v++) acc[i][j][v] = 0.f;

    int nt = K >> 5;

    auto load_tile = [&](int it, int st) {
        bf16* base = sm + st*STG128;
        const bf16* src = A + (size_t)(m0 + a_row)*K + it*32 + a_off;
        cp16(&base[a_row*AP + a_off],     src);
        cp16(&base[a_row*AP + a_off + 8], src + 8);
        #pragma unroll
        for (int s = 0; s < 2; s++) {
            int row = b_row0 + s*16;
            int col = n0 + b_off;
            if (col < N) {
                cp16(&base[OFF_B128 + row*BP + b_off], W + (size_t)(it*32 + row)*N + col);
            } else {
                *reinterpret_cast<uint4*>(&base[OFF_B128 + row*BP + b_off]) = make_uint4(0,0,0,0);
            }
        }
        asm volatile("cp.async.commit_group;");
    };

    load_tile(0, 0);
    load_tile(1, 1);

    int st = 0, st_next = 2;
    for (int it = 0; it < nt; it++) {
        if (it + 2 < nt) {
            load_tile(it + 2, st_next);
            asm volatile("cp.async.wait_group 2;");
        } else {
            asm volatile("cp.async.wait_group 0;");
        }
        __syncthreads();

        bf16* base = sm + st*STG128;
        #pragma unroll
        for (int kt = 0; kt < 2; kt++) {
            int kk = kt * 16;
            uint32_t af[4][4];
            #pragma unroll
            for (int mt = 0; mt < 4; mt++) {
                int r = wm*64 + mt*16 + (lane & 15);
                int c = kk + (lane >> 4)*8;
                ldsm4(af[mt], (uint32_t)__cvta_generic_to_shared(&base[r*AP + c]));
            }
            uint32_t bfr[2][4];
            #pragma unroll
            for (int np = 0; np < 2; np++) {
                int kr = kk + (lane & 15);
                int c  = wn*32 + np*16 + (lane >> 4)*8;
                ldsm4t(bfr[np], (uint32_t)__cvta_generic_to_shared(&base[OFF_B128 + kr*BP + c]));
            }
            #pragma unroll
            for (int mt = 0; mt < 4; mt++)
                #pragma unroll
                for (int nt2 = 0; nt2 < 4; nt2++) {
                    int np = nt2 >> 1, s = (nt2 & 1)*2;
                    mma_bf16(acc[mt][nt2], af[mt], bfr[np][s], bfr[np][s+1]);
                }
        }
        __syncthreads();
        st = (st == 2) ? 0 : st + 1;
        st_next = (st_next == 2) ? 0 : st_next + 1;
    }

    int gr = lane >> 2, gc = (lane & 3)*2;
    #pragma unroll
    for (int mt = 0; mt < 4; mt++) {
        #pragma unroll
        for (int nt2 = 0; nt2 < 4; nt2++) {
            int row0 = m0 + wm*64 + mt*16 + gr;
            int col0 = n0 + wn*32 + nt2*8 + gc;
            if (col0 < N) {
                C[(size_t)row0*N + col0]     = acc[mt][nt2][0];
                C[(size_t)(row0+8)*N + col0] = acc[mt][nt2][2];
            }
            if (col0 + 1 < N) {
                C[(size_t)row0*N + col0+1]     = acc[mt][nt2][1];
                C[(size_t)(row0+8)*N + col0+1] = acc[mt][nt2][3];
            }
        }
    }
}

// ---------------- 64x64 tile (small GEMMs), 4-stage pipeline ----------------
#define BP64 72
#define OFF_B64 (64*AP)
#define STG64   (64*AP + 32*BP64)

__global__ __launch_bounds__(256) void gemm64(const bf16* __restrict__ A,
                                              const bf16* __restrict__ W,
                                              const float* __restrict__ bias,
                                              const float* __restrict__ gate,
                                              float* __restrict__ C,
                                              int M, int N, int K,
                                              long wz, long cz) {
    __shared__ bf16 sm[4*STG64];

    W += (size_t)blockIdx.z * wz;
    C += (size_t)blockIdx.z * cz;

    int tid = threadIdx.x;
    int n0 = blockIdx.x * 64, m0 = blockIdx.y * 64;
    int warp = tid >> 5, lane = tid & 31;
    int wm = warp >> 2, wn = warp & 3;

    int a_row = tid >> 2, a_off = (tid & 3) * 8;
    int b_row = tid >> 3, b_off = (tid & 7) * 8;

    float acc[2][2][4];
    #pragma unroll
    for (int i = 0; i < 2; i++)
        #pragma unroll
        for (int j = 0; j < 2; j++)
            #pragma unroll
            for (int v = 0; v < 4; v++) acc[i][j][v] = 0.f;

    int nt = K >> 5;

    auto load_tile = [&](int it, int st) {
        bf16* base = sm + st*STG64;
        cp16(&base[a_row*AP + a_off], A + (size_t)(m0 + a_row)*K + it*32 + a_off);
        int col = n0 + b_off;
        if (col < N) {
            cp16(&base[OFF_B64 + b_row*BP64 + b_off], W + (size_t)(it*32 + b_row)*N + col);
        } else {
            *reinterpret_cast<uint4*>(&base[OFF_B64 + b_row*BP64 + b_off]) = make_uint4(0,0,0,0);
        }
        asm volatile("cp.async.commit_group;");
    };

    load_tile(0, 0);
    load_tile(1, 1);
    load_tile(2, 2);

    for (int it = 0; it < nt; it++) {
        if (it + 3 < nt) {
            load_tile(it + 3, (it + 3) & 3);
            asm volatile("cp.async.wait_group 3;");
        } else {
            asm volatile("cp.async.wait_group 0;");
        }
        __syncthreads();

        bf16* base = sm + (it & 3)*STG64;
        #pragma unroll
        for (int kt = 0; kt < 2; kt++) {
            int kk = kt * 16;
            uint32_t af[2][4];
            #pragma unroll
            for (int mt = 0; mt < 2; mt++) {
                int r = wm*32 + mt*16 + (lane & 15);
                int c = kk + (lane >> 4)*8;
                ldsm4(af[mt], (uint32_t)__cvta_generic_to_shared(&base[r*AP + c]));
            }
            uint32_t bfr[4];
            {
                int kr = kk + (lane & 15);
                int c  = wn*16 + (lane >> 4)*8;
                ldsm4t(bfr, (uint32_t)__cvta_generic_to_shared(&base[OFF_B64 + kr*BP64 + c]));
            }
            #pragma unroll
            for (int mt = 0; mt < 2; mt++)
                #pragma unroll
                for (int nt2 = 0; nt2 < 2; nt2++) {
                    int s = nt2*2;
                    mma_bf16(acc[mt][nt2], af[mt], bfr[s], bfr[s+1]);
                }
        }
        __syncthreads();
    }

    int gr = lane >> 2, gc = (lane & 3)*2;
    #pragma unroll
    for (int mt = 0; mt < 2; mt++) {
        int row0 = m0 + wm*32 + mt*16 + gr;
        int bidx = row0 / LL;
        #pragma unroll
        for (int nt2 = 0; nt2 < 2; nt2++) {
            int col0 = n0 + wn*16 + nt2*8 + gc;
            float b0 = bias ? bias[col0] : 0.f;
            float b1 = bias ? bias[col0+1] : 0.f;
            float v00 = acc[mt][nt2][0] + b0, v01 = acc[mt][nt2][1] + b1;
            float v10 = acc[mt][nt2][2] + b0, v11 = acc[mt][nt2][3] + b1;
            if (col0 < N) {
                if (gate) {
                    float gv0 = gate[bidx*6*DM + col0];
                    float gv1 = gate[bidx*6*DM + col0 + 1];
                    C[(size_t)row0*N + col0]       += gv0 * v00;
                    C[(size_t)row0*N + col0+1]     += gv1 * v01;
                    C[(size_t)(row0+8)*N + col0]   += gv0 * v10;
                    C[(size_t)(row0+8)*N + col0+1] += gv1 * v11;
                } else {
                    C[(size_t)row0*N + col0]       = v00;
                    C[(size_t)row0*N + col0+1]     = v01;
                    C[(size_t)(row0+8)*N + col0]   = v10;
                    C[(size_t)(row0+8)*N + col0+1] = v11;
                }
            }
        }
    }
}

// ---------------- pre-norm + AdaLN modulation (l==0 reads hs) ----------------
__global__ void k_prenorm_mod(int l, const float* __restrict__ hs,
                              const float* __restrict__ norm_w) {
    int t = blockIdx.x;
    int b = t / LL;
    const float* aff = &g_aff[(l*BB + b)*6*DM];
    float vals[3];
    float ss = 0.f;
    #pragma unroll
    for (int i = 0; i < 3; i++) {
        int d = threadIdx.x + i*256;
        float v = (l == 0) ? hs[t*DM + d]
                           : (g_resid[t*DM + d] + g_hidden[t*DM + d]);
        g_resid[t*DM + d] = v;
        vals[i] = v;
        ss += v*v;
    }
    ss = block_reduce_sum(ss);
    float rstd = rsqrtf(ss * (1.f/DM) + 1e-5f);
    #pragma unroll
    for (int i = 0; i < 3; i++) {
        int d = threadIdx.x + i*256;
        float x = vals[i] * rstd * norm_w[l*DM + d];
        g_hidden[t*DM + d] = x;
        g_u_bf[t*DM + d] = __float2bfloat16(x * (1.f + aff[DM + d]) + aff[d]);
    }
}

// ---------------- conv + dt: all 28 loads batched up front (explicit MLP) ----------------
__global__ void k_conv_dt(int l, const float* __restrict__ conv_w,
                          const float* __restrict__ conv_b,
                          const float* __restrict__ dt_bias,
                          const float* __restrict__ A_log) {
    int t  = blockIdx.x;
    int b  = t / LL, tt = t % LL;
    const float* base = g_zx + (size_t)(b*LL)*DIP + DI;

    // 7 channels per thread (CONVD = 7*256)
    float vin[4][7];
    #pragma unroll
    for (int j = 0; j < 4; j++) {
        int ts = tt - 3 + j;
        const float* row = base + (size_t)ts*DIP;
        #pragma unroll
        for (int i = 0; i < 7; i++) {
            int c = threadIdx.x + i*256;
            vin[j][i] = (ts >= 0) ? row[c] : 0.f;
        }
    }
    #pragma unroll
    for (int i = 0; i < 7; i++) {
        int c = threadIdx.x + i*256;
        const float* wc = conv_w + (l*CONVD + c)*4;
        float acc = conv_b[l*CONVD + c]
                  + wc[0]*vin[0][i] + wc[1]*vin[1][i]
                  + wc[2]*vin[2][i] + wc[3]*vin[3][i];
        g_xBC[(size_t)t*CONVD + c] = siluf(acc);
    }
    if (threadIdx.x < NH) {
        int hh = threadIdx.x;
        float x = g_zx[(size_t)t*DIP + DI + CONVD + hh] + dt_bias[l*NH + hh];
        float dt = (x > 20.f) ? x : log1pf(expf(x));
        g_dt[t*NH + hh] = dt;
        g_dA[t*NH + hh] = expf(-expf(A_log[l*NH + hh]) * dt);
    }
}

// ---------------- SSM scan: register-prefetch double-buffered ----------------
#define TCH 8
__global__ __launch_bounds__(256) void k_scan(int l, const float* __restrict__ D_ssm) {
    int bh = blockIdx.x;
    int b = bh / NH, hh = bh % NH;
    int ps = blockIdx.y;
    int tid = threadIdx.x;
    int pl = tid >> 3;
    int ng = tid & 7;
    int nb = ng * 16;
    float hreg[16];
    #pragma unroll
    for (int i = 0; i < 16; i++) hreg[i] = 0.f;

    __shared__ float sx[TCH][32];
    __shared__ float sB[TCH][DSTATE];
    __shared__ float sC[TCH][DSTATE];
    __shared__ float sdt[TCH], sdA[TCH];
    float Dh = D_ssm[l*NH + hh];

    int goff;
    if (tid < 32)       goff = hh*HD + ps*32 + tid;
    else if (tid < 160) goff = DI + tid - 32;
    else                goff = DI + DSTATE + tid - 160;
    int goff2 = DI + DSTATE + 96 + tid;

    float rv[TCH], rv2[TCH];
    float rdt = 0.f, rdA = 0.f;

    auto issue_loads = [&](int t0) {
        #pragma unroll
        for (int st = 0; st < TCH; st++) {
            const float* xb = g_xBC + (size_t)(b*LL + t0 + st)*CONVD;
            rv[st] = xb[goff];
            if (tid < 32) rv2[st] = xb[goff2];
        }
        if (tid < TCH) {
            int tok = b*LL + t0 + tid;
            rdt = g_dt[tok*NH + hh];
            rdA = g_dA[tok*NH + hh];
        }
    };

    issue_loads(0);

    for (int t0 = 0; t0 < LL; t0 += TCH) {
        #pragma unroll
        for (int st = 0; st < TCH; st++) {
            if (tid < 32)       { sx[st][tid] = rv[st]; sC[st][96+tid] = rv2[st]; }
            else if (tid < 160) sB[st][tid-32]  = rv[st];
            else                sC[st][tid-160] = rv[st];
        }
        if (tid < TCH) { sdt[tid] = rdt; sdA[tid] = rdA; }
        __syncthreads();
        if (t0 + TCH < LL) issue_loads(t0 + TCH);
        #pragma unroll
        for (int st = 0; st < TCH; st++) {
            float dtt = sdt[st], dAt = sdA[st];
            float xp  = sx[st][pl];
            float dbx = dtt * xp;
            float y = 0.f;
            #pragma unroll
            for (int i = 0; i < 16; i++) {
                float hv = hreg[i]*dAt + dbx*sB[st][nb+i];
                hreg[i] = hv;
                y += hv * sC[st][nb+i];
            }
            y += __shfl_xor_sync(0xffffffffu, y, 1);
            y += __shfl_xor_sync(0xffffffffu, y, 2);
            y += __shfl_xor_sync(0xffffffffu, y, 4);
            if (ng == 0) {
                int tok = b*LL + t0 + st;
                g_y[(size_t)tok*DI + hh*HD + ps*32 + pl] = y + xp * Dh;
            }
        }
        __syncthreads();
    }
}

// ---------------- gated RMS norm -> y bf16 ----------------
__global__ void k_gatenorm(int l, const float* __restrict__ ssm_norm_w) {
    int t = blockIdx.x;
    __shared__ float sv[DI];
    float ss = 0.f;
    for (int d = threadIdx.x; d < DI; d += 256) {
        float z = g_zx[(size_t)t*DIP + d];
        float v = g_y[(size_t)t*DI + d] * siluf(z);
        sv[d] = v;
        ss += v*v;
    }
    ss = block_reduce_sum(ss);
    float rstd = rsqrtf(ss * (1.f/DI) + 1e-5f);
    for (int d = threadIdx.x; d < DI; d += 256)
        g_y_bf[(size_t)t*DI + d] = __float2bfloat16(sv[d] * rstd * ssm_norm_w[l*DI + d]);
}

// ---------------- u = ln_noaffine(hidden)*(1+sc_msa)+sh_msa ----------------
__global__ void k_post_mamba(int l) {
    int t = blockIdx.x;
    int b = t / LL;
    const float* aff = &g_aff[(l*BB + b)*6*DM];
    float vals[3];
    float s1 = 0.f;
    #pragma unroll
    for (int i = 0; i < 3; i++) {
        int d = threadIdx.x + i*256;
        float v = g_hidden[t*DM + d];
        vals[i] = v;
        s1 += v;
    }
    s1 = block_reduce_sum(s1);
    float mean = s1 * (1.f/DM);
    float s2 = 0.f;
    #pragma unroll
    for (int i = 0; i < 3; i++) { float c = vals[i] - mean; s2 += c*c; }
    s2 = block_reduce_sum(s2);
    float rstd = rsqrtf(s2 * (1.f/DM) + 1e-6f);
    #pragma unroll
    for (int i = 0; i < 3; i++) {
        int d = threadIdx.x + i*256;
        float x = (vals[i] - mean) * rstd;
        g_u_bf[t*DM + d] = __float2bfloat16(x * (1.f + aff[4*DM + d]) + aff[3*DM + d]);
    }
}

// ---------------- cross attention ----------------
__global__ __launch_bounds__(512) void k_attn(int l) {
    int qt = blockIdx.x, hh = blockIdx.y, b = blockIdx.z;
    int warp = threadIdx.x >> 5, lane = threadIdx.x & 31;
    const float* kp = g_kall + (size_t)l*BB*LCC*AINNER;
    const float* vp = g_vall + (size_t)l*BB*LCC*AINNER;
    __shared__ float Ks[64][65];
    __shared__ float Vs[64][64];
    __shared__ float Qs[16][64];
    __shared__ float Ps[16][64];
    for (int idx = threadIdx.x; idx < 64*64; idx += 512) {
        int m = idx >> 6, d = idx & 63;
        Ks[m][d] = kp[(size_t)(b*LCC + m)*AINNER + hh*ADD + d];
        Vs[m][d] = vp[(size_t)(b*LCC + m)*AINNER + hh*ADD + d];
    }
    for (int idx = threadIdx.x; idx < 16*64; idx += 512) {
        int q = idx >> 6, d = idx & 63;
        Qs[q][d] = g_q[(size_t)(b*LL + qt*16 + q)*AINNER + hh*ADD + d];
    }
    __syncthreads();
    int q = warp;
    float s0 = 0.f, s1 = 0.f;
    #pragma unroll 8
    for (int d = 0; d < 64; d++) {
        float qd = Qs[q][d];
        s0 += qd * Ks[lane][d];
        s1 += qd * Ks[lane+32][d];
    }
    s0 *= 0.125f; s1 *= 0.125f;
    float mx = fmaxf(s0, s1);
    #pragma unroll
    for (int o = 16; o > 0; o >>= 1) mx = fmaxf(mx, __shfl_xor_sync(0xffffffffu, mx, o));
    float e0 = expf(s0 - mx), e1 = expf(s1 - mx);
    float sum = e0 + e1;
    #pragma unroll
    for (int o = 16; o > 0; o >>= 1) sum += __shfl_xor_sync(0xffffffffu, sum, o);
    float inv = 1.f / sum;
    Ps[q][lane] = e0 * inv;
    Ps[q][lane+32] = e1 * inv;
    __syncwarp();
    float o0 = 0.f, o1 = 0.f;
    #pragma unroll 8
    for (int m = 0; m < 64; m++) {
        float pm = Ps[q][m];
        o0 += pm * Vs[m][lane];
        o1 += pm * Vs[m][lane+32];
    }
    size_t base = (size_t)(b*LL + qt*16 + q)*AINNER + hh*ADD;
    g_ao_bf[base + lane]      = __float2bfloat16(o0);
    g_ao_bf[base + lane + 32] = __float2bfloat16(o1);
}

// ---------------- final rmsnorm ----------------
__global__ void k_final(const float* __restrict__ norm_f_w, float* __restrict__ out) {
    int t = blockIdx.x;
    float vals[3];
    float ss = 0.f;
    #pragma unroll
    for (int i = 0; i < 3; i++) {
        int d = threadIdx.x + i*256;
        float v = g_hidden[t*DM + d] + g_resid[t*DM + d];
        vals[i] = v;
        ss += v*v;
    }
    ss = block_reduce_sum(ss);
    float rstd = rsqrtf(ss * (1.f/DM) + 1e-5f);
    #pragma unroll
    for (int i = 0; i < 3; i++) {
        int d = threadIdx.x + i*256;
        out[t*DM + d] = vals[i] * rstd * norm_f_w[d];
    }
}

// ---------------- host ----------------
#define GETSYM(p, T, s) do { void* tmp_; cudaGetSymbolAddress(&tmp_, s); p = (T*)tmp_; } while(0)

extern "C" void kernel_launch(void* const* d_in, const int* in_sizes, int n_in,
                              void* d_out, int out_size) {
    const float* hs        = (const float*)d_in[0];
    const float* ref       = (const float*)d_in[1];
    const float* norm_w    = (const float*)d_in[2];
    const float* ada_w     = (const float*)d_in[3];
    const float* ada_b     = (const float*)d_in[4];
    const float* in_w      = (const float*)d_in[5];
    const float* conv_w    = (const float*)d_in[6];
    const float* conv_b    = (const float*)d_in[7];
    const float* dt_bias   = (const float*)d_in[8];
    const float* A_log     = (const float*)d_in[9];
    const float* D_ssm     = (const float*)d_in[10];
    const float* ssm_nw    = (const float*)d_in[11];
    const float* out_w     = (const float*)d_in[12];
    const float* out_b     = (const float*)d_in[13];
    const float* q_w       = (const float*)d_in[14];
    const float* k_w       = (const float*)d_in[15];
    const float* v_w       = (const float*)d_in[16];
    const float* o_w       = (const float*)d_in[17];
    const float* o_b       = (const float*)d_in[18];
    const float* norm_f_w  = (const float*)d_in[19];
    float* out = (float*)d_out;

    static int smem_set = 0;
    if (!smem_set) {
        cudaFuncSetAttribute(gemm128, cudaFuncAttributeMaxDynamicSharedMemorySize, SM128_BYTES);
        smem_set = 1;
    }

    float *p_zx, *p_q, *p_y, *p_kall, *p_vall, *p_hidden, *p_aff;
    GETSYM(p_zx,    float, g_zx);
    GETSYM(p_q,     float, g_q);
    GETSYM(p_y,     float, g_y);
    GETSYM(p_kall,  float, g_kall);
    GETSYM(p_vall,  float, g_vall);
    GETSYM(p_hidden,float, g_hidden);
    GETSYM(p_aff,   float, g_aff);

    bf16 *u_bf,*y_bf,*ao_bf,*ref_bf,*wi_bf,*wo_bf,*wq_bf,*wk_bf,*wv_bf,*wp_bf;
    GETSYM(u_bf,  bf16, g_u_bf);
    GETSYM(y_bf,  bf16, g_y_bf);
    GETSYM(ao_bf, bf16, g_ao_bf);
    GETSYM(ref_bf,bf16, g_ref_bf);
    GETSYM(wi_bf, bf16, g_wi_bf);
    GETSYM(wo_bf, bf16, g_wo_bf);
    GETSYM(wq_bf, bf16, g_wq_bf);
    GETSYM(wk_bf, bf16, g_wk_bf);
    GETSYM(wv_bf, bf16, g_wv_bf);
    GETSYM(wp_bf, bf16, g_wp_bf);

    const int M = BB*LL;   // 1024
    // all sizes here are multiples of 4
    #define CVT(src, dst, n) k_tobf16v<<<(((n)/4)+255)/256, 256>>>(src, dst, (n)/4)

    CVT(ref, ref_bf, BB*LCC*DM);
    CVT(k_w, wk_bf, NLAYER*DM*AINNER);
    CVT(v_w, wv_bf, NLAYER*DM*AINNER);
    gemm64<<<dim3(AINNER/64, (BB*LCC)/64, NLAYER), 256>>>(ref_bf, wk_bf, nullptr, nullptr,
        p_kall, BB*LCC, AINNER, DM, (long)DM*AINNER, (long)BB*LCC*AINNER);
    gemm64<<<dim3(AINNER/64, (BB*LCC)/64, NLAYER), 256>>>(ref_bf, wv_bf, nullptr, nullptr,
        p_vall, BB*LCC, AINNER, DM, (long)DM*AINNER, (long)BB*LCC*AINNER);
    k_condsilu<<<(BB*DM + 255)/256, 256>>>(ref);
    k_ada<<<(NLAYER*BB*6*DM + 255)/256, 256>>>(ada_w, ada_b);
    CVT(in_w,  wi_bf, NLAYER*DM*DIP);
    CVT(out_w, wo_bf, NLAYER*DI*DM);
    CVT(q_w,   wq_bf, NLAYER*DM*AINNER);
    CVT(o_w,   wp_bf, NLAYER*AINNER*DM);

    for (int l = 0; l < NLAYER; l++) {
        k_prenorm_mod<<<M, 256>>>(l, hs, norm_w);
        gemm128<<<dim3((DIP+127)/128, M/128), 256, SM128_BYTES>>>(u_bf,
            wi_bf + (size_t)l*DM*DIP, p_zx, M, DIP, DM, 0, 0);
        k_conv_dt<<<M, 256>>>(l, conv_w, conv_b, dt_bias, A_log);
        k_scan<<<dim3(BB*NH, 2), 256>>>(l, D_ssm);
        k_gatenorm<<<M, 256>>>(l, ssm_nw);
        gemm64<<<dim3(DM/64, M/64), 256>>>(y_bf, wo_bf + (size_t)l*DI*DM, out_b + l*DM,
            p_aff + (size_t)(l*BB)*6*DM + 2*DM, p_hidden, M, DM, DI, 0, 0);
        k_post_mamba<<<M, 256>>>(l);
        gemm64<<<dim3(AINNER/64, M/64), 256>>>(u_bf, wq_bf + (size_t)l*DM*AINNER, nullptr,
            nullptr, p_q, M, AINNER, DM, 0, 0);
        k_attn<<<dim3(LL/16, AHH, BB), 512>>>(l);
        gemm64<<<dim3(DM/64, M/64), 256>>>(ao_bf, wp_bf + (size_t)l*AINNER*DM, o_b + l*DM,
            p_aff + (size_t)(l*BB)*6*DM + 5*DM, p_hidden, M, DM, AINNER, 0, 0);
    }
    k_final<<<M, 256>>>(norm_f_w, out);
}